// round 15
// baseline (speedup 1.0000x reference)
#include <cuda_runtime.h>
#include <math.h>
#include <stdint.h>

#define BB 16
#define NN 1024
#define CC 64
#define CIN 16
#define PADN 68

typedef unsigned long long u64;

// ---------------- fp32x2 helpers (chanmix) ----------------
__device__ __forceinline__ u64 splat2(float v) {
    u64 r; asm("mov.b64 %0, {%1, %1};" : "=l"(r) : "f"(v)); return r;
}
__device__ __forceinline__ void ffma2(u64& d, u64 a, u64 b) {
    asm("fma.rn.f32x2 %0, %1, %2, %0;" : "+l"(d) : "l"(a), "l"(b));
}
__device__ __forceinline__ float2 unpack2(u64 v) {
    float2 r; asm("mov.b64 {%0, %1}, %2;" : "=f"(r.x), "=f"(r.y) : "l"(v)); return r;
}
__device__ __forceinline__ u64 pack2(float x, float y) {
    u64 r; asm("mov.b64 %0, {%1, %2};" : "=l"(r) : "f"(x), "f"(y)); return r;
}

// ---------------- mma.sync tf32 + cp.async helpers ----------------
__device__ __forceinline__ uint32_t smem_u32(const void* p) {
    uint32_t a;
    asm("{ .reg .u64 t; cvta.to.shared.u64 t, %1; cvt.u32.u64 %0, t; }" : "=r"(a) : "l"(p));
    return a;
}
__device__ __forceinline__ float rnd_tf32(float f) {
    uint32_t r; asm("cvt.rna.tf32.f32 %0, %1;" : "=r"(r) : "f"(f));
    return __uint_as_float(r);
}
#define LDSM4(r0, r1, r2, r3, addr)                                            \
    asm volatile("ldmatrix.sync.aligned.m8n8.x4.shared.b16 {%0,%1,%2,%3}, [%4];" \
        : "=r"(r0), "=r"(r1), "=r"(r2), "=r"(r3) : "r"(addr))
#define MMA_TF32(c, a0, a1, a2, a3, b0, b1)                                    \
    asm volatile("mma.sync.aligned.m16n8k8.row.col.f32.tf32.tf32.f32 "         \
        "{%0,%1,%2,%3}, {%4,%5,%6,%7}, {%8,%9}, {%0,%1,%2,%3};"                \
        : "+f"((c)[0]), "+f"((c)[1]), "+f"((c)[2]), "+f"((c)[3])               \
        : "r"(a0), "r"(a1), "r"(a2), "r"(a3), "r"(b0), "r"(b1))
__device__ __forceinline__ void cp16(uint32_t dst, const void* src) {
    asm volatile("cp.async.cg.shared.global [%0], [%1], 16;" :: "r"(dst), "l"(src));
}
#define CP_COMMIT()  asm volatile("cp.async.commit_group;" ::: "memory")
#define CP_WAIT1()   asm volatile("cp.async.wait_group 1;" ::: "memory")
#define CP_WAIT0()   asm volatile("cp.async.wait_group 0;" ::: "memory")

// ---------------- static device scratch ----------------
__device__ float g_gl  [BB*NN*NN];
__device__ float g_g1  [NN*NN];
__device__ float g_g2  [NN*NN];
__device__ float g_wr  [NN*NN];
__device__ float g_d   [2*NN];
__device__ float g_h0a [BB*CC*NN];
__device__ float g_hT  [BB*CC*NN];
__device__ float g_xuai[BB*CC*NN];
__device__ float g_xuaiT[BB*NN*CC];
__device__ float g_pa  [BB*CC*NN];
__device__ float g_pb  [BB*CC*NN];
__device__ float g_pc  [BB*CC*NN];
__device__ float g_pd  [BB*CC*NN];
__device__ float g_l12 [BB*2*CC*NN];
__device__ float g_l12s[BB*2*CC*NN];
__device__ float g_t12a[BB*2*CC*NN];
__device__ float g_t12b[BB*2*CC*NN];
__device__ float g_u12 [BB*2*CC*NN];
__device__ float g_a12a[BB*2*CC*NN];
__device__ float g_a12b[BB*2*CC*NN];
__device__ float g_sxa [BB*2*CC*NN];
__device__ float g_sxb [BB*2*CC*NN];
__device__ float g_s1  [BB*NN];
__device__ float g_s2  [BB*NN];
__device__ float g_amx [BB*NN];
__device__ float g_ainv[BB*NN];
__device__ float g_sq  [BB*NN];
__device__ float g_part[BB*8*NN];
__device__ float g_stats[2*BB*2];

#define TPAD 20
#define BUFSTRIDE (128*TPAD*4)

// =========================================================================
// mma_gemm (tf32, 2-stage cp.async): C_ks[b,c,n] = sum_{k in split} A*B
// =========================================================================
__global__ void __launch_bounds__(256, 2)
mma_gemm(const float* __restrict__ A, size_t aBatch, int mvalid,
         const float* __restrict__ B, size_t bBatch, int nsplit,
         const float* __restrict__ add0, const float* __restrict__ add1,
         const float* __restrict__ biasN,
         float* __restrict__ C0, float* __restrict__ C1,
         float* __restrict__ C2, float* __restrict__ C3, size_t cBatch)
{
    __shared__ uint32_t As[2][128*TPAD];
    __shared__ uint32_t Bs[2][128*TPAD];

    const int tid  = threadIdx.x;
    const int lane = tid & 31;
    const int wid  = tid >> 5;
    const int bidx = blockIdx.y;
    const int n0   = blockIdx.x * 128;
    const int ks   = blockIdx.z;
    const int kPer = NN / nsplit;
    const int T    = kPer / 16;
    const int k0b  = ks * kPer;

    const float* Ab = A + (size_t)bidx * aBatch + k0b;
    const float* Bb = B + (size_t)bidx * bBatch + (size_t)n0 * NN + k0b;

    const int frow0 = tid >> 2;
    const int frow1 = 64 + (tid >> 2);
    const int fkq   = (tid & 3) * 4;

    const float* aP0 = Ab + (size_t)frow0 * NN + fkq;
    const float* aP1 = Ab + (size_t)((frow1 < mvalid) ? frow1 : 0) * NN + fkq;
    const float* bP0 = Bb + (size_t)frow0 * NN + fkq;
    const float* bP1 = Bb + (size_t)frow1 * NN + fkq;

    const uint32_t aSm = smem_u32(&As[0][0]);
    const uint32_t bSm = smem_u32(&Bs[0][0]);
    const uint32_t aFill  = aSm + (frow0*TPAD + fkq) * 4;
    const uint32_t aFill1 = aSm + (frow1*TPAD + fkq) * 4;
    const uint32_t bFill  = bSm + (frow0*TPAD + fkq) * 4;
    const uint32_t bFill1 = bSm + (frow1*TPAD + fkq) * 4;

    const int aRowOff = (lane & 15) * TPAD + (lane >> 4) * 4;
    const int bRowOff = ((lane >> 4) * 8 + (lane & 7)) * TPAD + ((lane >> 3) & 1) * 4;

    const int mbase = (wid >> 2) * 64;
    const int nbase = (wid & 3) * 32;

    float c[4][4][4];
#pragma unroll
    for (int i = 0; i < 4; i++)
#pragma unroll
        for (int j = 0; j < 4; j++)
#pragma unroll
            for (int q = 0; q < 4; q++) c[i][j][q] = 0.f;

    cp16(aFill,  aP0); cp16(aFill1, aP1);
    cp16(bFill,  bP0); cp16(bFill1, bP1);
    CP_COMMIT();

    for (int t = 0; t < T; ++t) {
        const int cur = t & 1;
        if (t + 1 < T) {
            const uint32_t off = (uint32_t)((t+1) & 1) * BUFSTRIDE;
            const int ko = (t + 1) * 16;
            cp16(aFill  + off, aP0 + ko);
            cp16(aFill1 + off, aP1 + ko);
            cp16(bFill  + off, bP0 + ko);
            cp16(bFill1 + off, bP1 + ko);
            CP_COMMIT();
            CP_WAIT1();
        } else {
            CP_WAIT0();
        }
        __syncthreads();
        {
            const uint32_t aCur = aSm + cur * BUFSTRIDE;
            const uint32_t bCur = bSm + cur * BUFSTRIDE;
#pragma unroll
            for (int kk = 0; kk < 16; kk += 8) {
                uint32_t a[4][4];
#pragma unroll
                for (int mt = 0; mt < 4; mt++) {
                    uint32_t addr = aCur + ((mbase + mt*16)*TPAD + aRowOff + kk) * 4;
                    LDSM4(a[mt][0], a[mt][1], a[mt][2], a[mt][3], addr);
                }
                uint32_t bfr[4][2];
#pragma unroll
                for (int np = 0; np < 2; np++) {
                    uint32_t addr = bCur + ((nbase + np*16)*TPAD + bRowOff + kk) * 4;
                    LDSM4(bfr[np*2][0], bfr[np*2][1], bfr[np*2+1][0], bfr[np*2+1][1], addr);
                }
#pragma unroll
                for (int mt = 0; mt < 4; mt++)
#pragma unroll
                    for (int nt = 0; nt < 4; nt++)
                        MMA_TF32(c[mt][nt], a[mt][0], a[mt][1], a[mt][2], a[mt][3],
                                 bfr[nt][0], bfr[nt][1]);
            }
        }
        __syncthreads();
    }

    if (mbase >= mvalid) return;
    float* C = (ks == 0) ? C0 : (ks == 1) ? C1 : (ks == 2) ? C2 : C3;
    const float* add = (ks == 0) ? add0 : (ks == 1) ? add1 : nullptr;
    float* Cb = C + (size_t)bidx * cBatch;
    const float* Adb = add ? add + (size_t)bidx * cBatch : nullptr;
    const int gid = lane >> 2, tq = lane & 3;
#pragma unroll
    for (int mt = 0; mt < 4; mt++) {
        const int r = mbase + mt*16 + gid;
#pragma unroll
        for (int nt = 0; nt < 4; nt++) {
            const int col = n0 + nbase + nt*8 + tq*2;
            float2 v0 = { c[mt][nt][0], c[mt][nt][1] };
            float2 v1 = { c[mt][nt][2], c[mt][nt][3] };
            if (biasN && ks == 0) {
                float b0 = biasN[col], b1 = biasN[col+1];
                v0.x += b0; v0.y += b1; v1.x += b0; v1.y += b1;
            }
            if (Adb) {
                float2 d0 = *(const float2*)(Adb + (size_t)r * NN + col);
                float2 d1 = *(const float2*)(Adb + (size_t)(r+8) * NN + col);
                v0.x += d0.x; v0.y += d0.y; v1.x += d1.x; v1.y += d1.y;
            }
            *(float2*)(Cb + (size_t)r * NN + col)     = v0;
            *(float2*)(Cb + (size_t)(r+8) * NN + col) = v1;
        }
    }
}

// =========================================================================
// mma_gemm2 (2-stage): two independent GEMM units (unit = z>>1, ks = z&1).
// =========================================================================
__global__ void __launch_bounds__(256, 2)
mma_gemm2(const float* __restrict__ A0, const float* __restrict__ B0, size_t bS0,
          const float* __restrict__ A1, const float* __restrict__ B1, size_t bS1,
          float* __restrict__ C00, float* __restrict__ C01,
          float* __restrict__ C10, float* __restrict__ C11, size_t cBatch)
{
    __shared__ uint32_t As[2][128*TPAD];
    __shared__ uint32_t Bs[2][128*TPAD];

    const int tid  = threadIdx.x;
    const int lane = tid & 31;
    const int wid  = tid >> 5;
    const int bidx = blockIdx.y;
    const int n0   = blockIdx.x * 128;
    const int unit = blockIdx.z >> 1;
    const int ks   = blockIdx.z & 1;
    const int k0b  = ks * 512;
    const int T    = 32;

    const float* A = unit ? A1 : A0;
    const float* B = unit ? B1 : B0;
    const size_t bBatch = unit ? bS1 : bS0;

    const float* Ab = A + (size_t)bidx * (size_t)(2*CC)*NN + k0b;
    const float* Bb = B + (size_t)bidx * bBatch + (size_t)n0 * NN + k0b;

    const int frow0 = tid >> 2;
    const int frow1 = 64 + (tid >> 2);
    const int fkq   = (tid & 3) * 4;

    const float* aP0 = Ab + (size_t)frow0 * NN + fkq;
    const float* aP1 = Ab + (size_t)frow1 * NN + fkq;
    const float* bP0 = Bb + (size_t)frow0 * NN + fkq;
    const float* bP1 = Bb + (size_t)frow1 * NN + fkq;

    const uint32_t aSm = smem_u32(&As[0][0]);
    const uint32_t bSm = smem_u32(&Bs[0][0]);
    const uint32_t aFill  = aSm + (frow0*TPAD + fkq) * 4;
    const uint32_t aFill1 = aSm + (frow1*TPAD + fkq) * 4;
    const uint32_t bFill  = bSm + (frow0*TPAD + fkq) * 4;
    const uint32_t bFill1 = bSm + (frow1*TPAD + fkq) * 4;

    const int aRowOff = (lane & 15) * TPAD + (lane >> 4) * 4;
    const int bRowOff = ((lane >> 4) * 8 + (lane & 7)) * TPAD + ((lane >> 3) & 1) * 4;

    const int mbase = (wid >> 2) * 64;
    const int nbase = (wid & 3) * 32;

    float c[4][4][4];
#pragma unroll
    for (int i = 0; i < 4; i++)
#pragma unroll
        for (int j = 0; j < 4; j++)
#pragma unroll
            for (int q = 0; q < 4; q++) c[i][j][q] = 0.f;

    cp16(aFill,  aP0); cp16(aFill1, aP1);
    cp16(bFill,  bP0); cp16(bFill1, bP1);
    CP_COMMIT();

    for (int t = 0; t < T; ++t) {
        const int cur = t & 1;
        if (t + 1 < T) {
            const uint32_t off = (uint32_t)((t+1) & 1) * BUFSTRIDE;
            const int ko = (t + 1) * 16;
            cp16(aFill  + off, aP0 + ko);
            cp16(aFill1 + off, aP1 + ko);
            cp16(bFill  + off, bP0 + ko);
            cp16(bFill1 + off, bP1 + ko);
            CP_COMMIT();
            CP_WAIT1();
        } else {
            CP_WAIT0();
        }
        __syncthreads();
        {
            const uint32_t aCur = aSm + cur * BUFSTRIDE;
            const uint32_t bCur = bSm + cur * BUFSTRIDE;
#pragma unroll
            for (int kk = 0; kk < 16; kk += 8) {
                uint32_t a[4][4];
#pragma unroll
                for (int mt = 0; mt < 4; mt++) {
                    uint32_t addr = aCur + ((mbase + mt*16)*TPAD + aRowOff + kk) * 4;
                    LDSM4(a[mt][0], a[mt][1], a[mt][2], a[mt][3], addr);
                }
                uint32_t bfr[4][2];
#pragma unroll
                for (int np = 0; np < 2; np++) {
                    uint32_t addr = bCur + ((nbase + np*16)*TPAD + bRowOff + kk) * 4;
                    LDSM4(bfr[np*2][0], bfr[np*2][1], bfr[np*2+1][0], bfr[np*2+1][1], addr);
                }
#pragma unroll
                for (int mt = 0; mt < 4; mt++)
#pragma unroll
                    for (int nt = 0; nt < 4; nt++)
                        MMA_TF32(c[mt][nt], a[mt][0], a[mt][1], a[mt][2], a[mt][3],
                                 bfr[nt][0], bfr[nt][1]);
            }
        }
        __syncthreads();
    }

    float* C = unit ? (ks ? C11 : C10) : (ks ? C01 : C00);
    float* Cb = C + (size_t)bidx * cBatch;
    const int gid = lane >> 2, tq = lane & 3;
#pragma unroll
    for (int mt = 0; mt < 4; mt++) {
        const int r = mbase + mt*16 + gid;
#pragma unroll
        for (int nt = 0; nt < 4; nt++) {
            const int col = n0 + nbase + nt*8 + tq*2;
            float2 v0 = { c[mt][nt][0], c[mt][nt][1] };
            float2 v1 = { c[mt][nt][2], c[mt][nt][3] };
            *(float2*)(Cb + (size_t)r * NN + col)     = v0;
            *(float2*)(Cb + (size_t)(r+8) * NN + col) = v1;
        }
    }
}

// =========================================================================
// mma_gemm_att: attention MMA with on-the-fly B generation (2-stage).
// =========================================================================
__device__ __forceinline__ float attval(float s1v, float s2v, float m, float iv) {
    float e = s1v + s2v;
    e = (e > 0.f) ? e : 0.01f * e;
    return rnd_tf32(__expf(e - m) * iv);
}

__global__ void __launch_bounds__(256, 2)
mma_gemm_att(const float* __restrict__ A, size_t aBatch,
             float* __restrict__ C0, float* __restrict__ C1, size_t cBatch)
{
    __shared__ uint32_t As[2][128*TPAD];
    __shared__ float    Bs[2][128*TPAD];

    const int tid  = threadIdx.x;
    const int lane = tid & 31;
    const int wid  = tid >> 5;
    const int bidx = blockIdx.y;
    const int n0   = blockIdx.x * 128;
    const int ks   = blockIdx.z;
    const int k0b  = ks * 512;
    const int T    = 32;

    const float* Ab = A + (size_t)bidx * aBatch + k0b;

    const int frow0 = tid >> 2;
    const int frow1 = 64 + (tid >> 2);
    const int fkq   = (tid & 3) * 4;

    const float* aP0 = Ab + (size_t)frow0 * NN + fkq;
    const float* aP1 = Ab;

    const float s1v0 = g_s1 [bidx*NN + n0 + frow0];
    const float m0   = g_amx[bidx*NN + n0 + frow0];
    const float iv0  = g_ainv[bidx*NN + n0 + frow0];
    const float s1v1 = g_s1 [bidx*NN + n0 + frow1];
    const float m1   = g_amx[bidx*NN + n0 + frow1];
    const float iv1  = g_ainv[bidx*NN + n0 + frow1];
    const float* s2p = g_s2 + bidx*NN + k0b + fkq;

    const uint32_t aSm = smem_u32(&As[0][0]);
    const uint32_t bSm = smem_u32(&Bs[0][0]);
    const uint32_t aFill  = aSm + (frow0*TPAD + fkq) * 4;
    const uint32_t aFill1 = aSm + (frow1*TPAD + fkq) * 4;

    const int aRowOff = (lane & 15) * TPAD + (lane >> 4) * 4;
    const int bRowOff = ((lane >> 4) * 8 + (lane & 7)) * TPAD + ((lane >> 3) & 1) * 4;

    const int mbase = (wid >> 2) * 64;
    const int nbase = (wid & 3) * 32;

    float c[4][4][4];
#pragma unroll
    for (int i = 0; i < 4; i++)
#pragma unroll
        for (int j = 0; j < 4; j++)
#pragma unroll
            for (int q = 0; q < 4; q++) c[i][j][q] = 0.f;

    cp16(aFill,  aP0); cp16(aFill1, aP1 + fkq);
    CP_COMMIT();
    {
        float4 s2v = *(const float4*)(s2p);
        float4 b0 = { attval(s1v0, s2v.x, m0, iv0), attval(s1v0, s2v.y, m0, iv0),
                      attval(s1v0, s2v.z, m0, iv0), attval(s1v0, s2v.w, m0, iv0) };
        float4 b1 = { attval(s1v1, s2v.x, m1, iv1), attval(s1v1, s2v.y, m1, iv1),
                      attval(s1v1, s2v.z, m1, iv1), attval(s1v1, s2v.w, m1, iv1) };
        *(float4*)&Bs[0][frow0*TPAD + fkq] = b0;
        *(float4*)&Bs[0][frow1*TPAD + fkq] = b1;
    }
    __syncthreads();

    for (int t = 0; t < T; ++t) {
        const int cur = t & 1;
        if (t + 1 < T) {
            const int nxt = (t+1) & 1;
            const uint32_t off = (uint32_t)nxt * BUFSTRIDE;
            const int ko = (t + 1) * 16;
            cp16(aFill  + off, aP0 + ko);
            cp16(aFill1 + off, aP1 + ko + fkq);
            CP_COMMIT();
            float4 s2v = *(const float4*)(s2p + ko);
            float4 b0 = { attval(s1v0, s2v.x, m0, iv0), attval(s1v0, s2v.y, m0, iv0),
                          attval(s1v0, s2v.z, m0, iv0), attval(s1v0, s2v.w, m0, iv0) };
            float4 b1 = { attval(s1v1, s2v.x, m1, iv1), attval(s1v1, s2v.y, m1, iv1),
                          attval(s1v1, s2v.z, m1, iv1), attval(s1v1, s2v.w, m1, iv1) };
            *(float4*)&Bs[nxt][frow0*TPAD + fkq] = b0;
            *(float4*)&Bs[nxt][frow1*TPAD + fkq] = b1;
            CP_WAIT1();
        } else {
            CP_WAIT0();
        }
        __syncthreads();
        {
            const uint32_t aCur = aSm + cur * BUFSTRIDE;
            const uint32_t bCur = bSm + cur * BUFSTRIDE;
#pragma unroll
            for (int kk = 0; kk < 16; kk += 8) {
                uint32_t a[4][4];
#pragma unroll
                for (int mt = 0; mt < 4; mt++) {
                    uint32_t addr = aCur + ((mbase + mt*16)*TPAD + aRowOff + kk) * 4;
                    LDSM4(a[mt][0], a[mt][1], a[mt][2], a[mt][3], addr);
                }
                uint32_t bfr[4][2];
#pragma unroll
                for (int np = 0; np < 2; np++) {
                    uint32_t addr = bCur + ((nbase + np*16)*TPAD + bRowOff + kk) * 4;
                    LDSM4(bfr[np*2][0], bfr[np*2][1], bfr[np*2+1][0], bfr[np*2+1][1], addr);
                }
#pragma unroll
                for (int mt = 0; mt < 4; mt++)
#pragma unroll
                    for (int nt = 0; nt < 4; nt++)
                        MMA_TF32(c[mt][nt], a[mt][0], a[mt][1], a[mt][2], a[mt][3],
                                 bfr[nt][0], bfr[nt][1]);
            }
        }
        __syncthreads();
    }

    if (mbase >= 64) return;
    float* Cb = (ks ? C1 : C0) + (size_t)bidx * cBatch;
    const int gid = lane >> 2, tq = lane & 3;
#pragma unroll
    for (int mt = 0; mt < 4; mt++) {
        const int r = mbase + mt*16 + gid;
#pragma unroll
        for (int nt = 0; nt < 4; nt++) {
            const int col = n0 + nbase + nt*8 + tq*2;
            float2 v0 = { c[mt][nt][0], c[mt][nt][1] };
            float2 v1 = { c[mt][nt][2], c[mt][nt][3] };
            *(float2*)(Cb + (size_t)r * NN + col)     = v0;
            *(float2*)(Cb + (size_t)(r+8) * NN + col) = v1;
        }
    }
}

// =========================================================================
// k_gram_mma: gl = transform( XtT @ XtT^T ), row partial sums fused.
// =========================================================================
#define GSTRIDE_W 68
__global__ void __launch_bounds__(256)
k_gram_mma()
{
    extern __shared__ uint32_t gsm[];
    __shared__ float rowsW[8][64];

    const int tid  = threadIdx.x;
    const int lane = tid & 31;
    const int wid  = tid >> 5;
    const int b  = blockIdx.z;
    const int i0 = blockIdx.x * 128;
    const int jb = blockIdx.y;
    const int j0 = jb * 128;

    const float* XT = g_xuaiT + (size_t)b * NN * CC;
    const uint32_t aSm = smem_u32(&gsm[0]);
    const uint32_t bSm = aSm + 128*GSTRIDE_W*4;

#pragma unroll
    for (int q = 0; q < 8; q++) {
        int f = q * 256 + tid;
        int row = f >> 4, seg = (f & 15) * 4;
        cp16(aSm + (row*GSTRIDE_W + seg) * 4, XT + (size_t)(i0 + row) * CC + seg);
        cp16(bSm + (row*GSTRIDE_W + seg) * 4, XT + (size_t)(j0 + row) * CC + seg);
    }
    CP_COMMIT();
    CP_WAIT0();
    __syncthreads();

    const int aRowOff = (lane & 15) * GSTRIDE_W + (lane >> 4) * 4;
    const int bRowOff = ((lane >> 4) * 8 + (lane & 7)) * GSTRIDE_W + ((lane >> 3) & 1) * 4;
    const int mbase = (wid >> 2) * 64;
    const int nbase = (wid & 3) * 32;

    float c[4][4][4];
#pragma unroll
    for (int i = 0; i < 4; i++)
#pragma unroll
        for (int j = 0; j < 4; j++)
#pragma unroll
            for (int q = 0; q < 4; q++) c[i][j][q] = 0.f;

#pragma unroll
    for (int kk = 0; kk < 64; kk += 8) {
        uint32_t a[4][4];
#pragma unroll
        for (int mt = 0; mt < 4; mt++) {
            uint32_t addr = aSm + ((mbase + mt*16)*GSTRIDE_W + aRowOff + kk) * 4;
            LDSM4(a[mt][0], a[mt][1], a[mt][2], a[mt][3], addr);
        }
        uint32_t bfr[4][2];
#pragma unroll
        for (int np = 0; np < 2; np++) {
            uint32_t addr = bSm + ((nbase + np*16)*GSTRIDE_W + bRowOff + kk) * 4;
            LDSM4(bfr[np*2][0], bfr[np*2][1], bfr[np*2+1][0], bfr[np*2+1][1], addr);
        }
#pragma unroll
        for (int mt = 0; mt < 4; mt++)
#pragma unroll
            for (int nt = 0; nt < 4; nt++)
                MMA_TF32(c[mt][nt], a[mt][0], a[mt][1], a[mt][2], a[mt][3],
                         bfr[nt][0], bfr[nt][1]);
    }

    const float* sq = g_sq + b*NN;
    float* glb = g_gl + (size_t)b*NN*NN;
    const int gid = lane >> 2, tq = lane & 3;
#pragma unroll
    for (int mt = 0; mt < 4; mt++) {
        const int rl = mbase + mt*16 + gid;
        const int gi0 = i0 + rl, gi1 = gi0 + 8;
        const float sqa = sq[gi0], sqb = sq[gi1];
        float rp0 = 0.f, rp1 = 0.f;
#pragma unroll
        for (int nt = 0; nt < 4; nt++) {
            const int col = j0 + nbase + nt*8 + tq*2;
            const float sj0 = sq[col], sj1 = sq[col+1];
            float d00 = fmaxf(sqa + sj0 - 2.f*c[mt][nt][0], 0.f);
            float d01 = fmaxf(sqa + sj1 - 2.f*c[mt][nt][1], 0.f);
            float d10 = fmaxf(sqb + sj0 - 2.f*c[mt][nt][2], 0.f);
            float d11 = fmaxf(sqb + sj1 - 2.f*c[mt][nt][3], 0.f);
            float v00 = rnd_tf32(__expf(__expf(-d00*(1.f/128.f)) + ((gi0 == col)   ? 1.f : 0.f)));
            float v01 = rnd_tf32(__expf(__expf(-d01*(1.f/128.f)) + ((gi0 == col+1) ? 1.f : 0.f)));
            float v10 = rnd_tf32(__expf(__expf(-d10*(1.f/128.f)) + ((gi1 == col)   ? 1.f : 0.f)));
            float v11 = rnd_tf32(__expf(__expf(-d11*(1.f/128.f)) + ((gi1 == col+1) ? 1.f : 0.f)));
            float2 w0 = {v00, v01}, w1 = {v10, v11};
            *(float2*)(glb + (size_t)gi0 * NN + col) = w0;
            *(float2*)(glb + (size_t)gi1 * NN + col) = w1;
            rp0 += v00 + v01;
            rp1 += v10 + v11;
        }
        rp0 += __shfl_xor_sync(0xffffffffu, rp0, 1, 4);
        rp0 += __shfl_xor_sync(0xffffffffu, rp0, 2, 4);
        rp1 += __shfl_xor_sync(0xffffffffu, rp1, 1, 4);
        rp1 += __shfl_xor_sync(0xffffffffu, rp1, 2, 4);
        if (tq == 0) {
            rowsW[wid][mt*16 + gid]     = rp0;
            rowsW[wid][mt*16 + gid + 8] = rp1;
        }
    }
    __syncthreads();
    if (tid < 128) {
        int half = tid >> 6, lr = tid & 63;
        float s = rowsW[half*4 + 0][lr] + rowsW[half*4 + 1][lr]
                + rowsW[half*4 + 2][lr] + rowsW[half*4 + 3][lr];
        g_part[((size_t)b*8 + jb)*NN + i0 + tid] = s;
    }
}

// ---------------- k_prep: lapT (y=0,1) + wround (y=2) + emb1 (y=3) ----------------
__global__ void k_prep(const float* __restrict__ graph, const float* __restrict__ emb2_w,
                       const float* __restrict__ x, const float* __restrict__ emb_w,
                       const float* __restrict__ emb_b) {
    __shared__ float w[CC*CIN];
    __shared__ float bsm[CC];
    const int plane = blockIdx.y;
    const int t = threadIdx.x;
    if (plane < 2) {
        int kg = plane, m = blockIdx.x;
        const float* src = graph + (size_t)kg*NN*NN + (size_t)m*NN;
        float* dst = ((kg == 0) ? g_g1 : g_g2) + (size_t)m*NN;
        const float* d = g_d + kg*NN;
        float dm = d[m];
#pragma unroll
        for (int q = 0; q < 4; q++) {
            int k = t + 256*q;
            float v = src[k] + ((m == k) ? 1.f : 0.f);
            dst[k] = rnd_tf32(v * dm * d[k]);
        }
    } else if (plane == 2) {
        size_t i = ((size_t)blockIdx.x * 256 + t) * 4;
        float4 v = *(const float4*)(emb2_w + i);
        float4 ww = { rnd_tf32(v.x), rnd_tf32(v.y), rnd_tf32(v.z), rnd_tf32(v.w) };
        *(float4*)(g_wr + i) = ww;
    } else {
        for (int i = t; i < CC*CIN; i += 256) w[i] = emb_w[i];
        if (t < CC) bsm[t] = emb_b[t];
        __syncthreads();
        int idx = blockIdx.x;
        int b = idx & 15;
        int n = ((idx >> 4) & 3) * 256 + t;
        int e0 = (idx >> 6) * 4;
        float xv[CIN];
        const float* xp = x + (size_t)b*CIN*NN + n;
#pragma unroll
        for (int c = 0; c < CIN; c++) xv[c] = xp[(size_t)c*NN];
        float* out = g_h0a + (size_t)b*CC*NN + n;
#pragma unroll
        for (int e = e0; e < e0 + 4; e++) {
            float s = bsm[e];
#pragma unroll
            for (int c = 0; c < CIN; c++) s = fmaf(w[e*CIN + c], xv[c], s);
            float lv = (s > 0.f) ? s : 0.01f*s;
            out[(size_t)e*NN] = rnd_tf32(lv);
        }
    }
}

// ---------------- laplacian d ----------------
__global__ void k_lap_d(const float* __restrict__ graph) {
    int i = blockIdx.x, k = blockIdx.y, t = threadIdx.x;
    const float* row = graph + (size_t)k*NN*NN + (size_t)i*NN;
    float s = 0.f;
    for (int j = t; j < NN; j += 256) s += row[j];
    __shared__ float sh[256];
    sh[t] = s; __syncthreads();
    for (int o = 128; o > 0; o >>= 1) { if (t < o) sh[t] += sh[t+o]; __syncthreads(); }
    if (t == 0) g_d[k*NN + i] = rsqrtf(sh[0] + 1.0f);
}

// ------- 64x64 channel mix, 256 threads, in-block K-split (2 warp-halves).
//         optional fused s1/s2, sq, coalesced transposed output,
//         2nd output with row-sum-derived scale (from g_part) -------
__global__ void __launch_bounds__(256)
chanmixD(const float* __restrict__ in, const float* __restrict__ in2,
         const float* __restrict__ in3, const float* __restrict__ in4,
         int reluIn, size_t inBstride, size_t inZoff,
         const float* __restrict__ Wa, const float* __restrict__ ba,
         const float* __restrict__ Wb, const float* __restrict__ bb_,
         int trans, int roundOut, float* __restrict__ out, size_t outBstride,
         float* __restrict__ out2, int scaleFromPart,
         const float* __restrict__ attA, float* __restrict__ s1o,
         float* __restrict__ s2o, float* __restrict__ sqo,
         float* __restrict__ xTo) {
    const int z = blockIdx.z;
    const float* W    = z ? Wb  : Wa;
    const float* bias = z ? bb_ : ba;
    const int b = blockIdx.y, n0 = blockIdx.x * 64;
    __shared__ float Ms[64*PADN];
    __shared__ float Xs[64*PADN];
    __shared__ float redA[8*64];
    __shared__ float redB[8*64];
    __shared__ float a1s[64], a2s[64];
    __shared__ float scInv[64];
    const int tid = threadIdx.x;     // 0..255
    const int wh  = tid >> 7;        // k-half: 0 or 1
    const int tl  = tid & 127;
    for (int i = tid; i < 64*64; i += 256) {
        int o = i >> 6, k = i & 63;
        Ms[k*PADN + o] = trans ? W[k*64 + o] : W[o*64 + k];
    }
    if (attA) {
        if (tid < 64) a1s[tid] = attA[tid];
        else if (tid < 128) a2s[tid-64] = attA[tid];
    }
    if (scaleFromPart && tid < 64) {
        float s = 0.f;
#pragma unroll
        for (int j = 0; j < 8; j++) s += g_part[((size_t)b*8 + j)*NN + n0 + tid];
        scInv[tid] = 1.f / s;
    }
    const size_t boff = (size_t)b*inBstride + (size_t)z*inZoff + n0;
    for (int i = tid; i < 64*16; i += 256) {
        int k = i >> 4, n4 = (i & 15) * 4;
        size_t off = boff + (size_t)k*NN + n4;
        float4 v = *(const float4*)(in + off);
        if (in2) { float4 w2 = *(const float4*)(in2 + off); v.x+=w2.x; v.y+=w2.y; v.z+=w2.z; v.w+=w2.w; }
        if (in3) { float4 w3 = *(const float4*)(in3 + off); v.x+=w3.x; v.y+=w3.y; v.z+=w3.z; v.w+=w3.w; }
        if (in4) { float4 w4 = *(const float4*)(in4 + off); v.x+=w4.x; v.y+=w4.y; v.z+=w4.z; v.w+=w4.w; }
        if (reluIn) {
            v.x = fmaxf(v.x, 0.f); v.y = fmaxf(v.y, 0.f);
            v.z = fmaxf(v.z, 0.f); v.w = fmaxf(v.w, 0.f);
        }
        *(float4*)&Xs[k*PADN + n4] = v;
    }
    __syncthreads();
    const int tx = tl & 15, ty = tl >> 4;
    u64 acc[4][4] = {};
    const int kbase = wh * 32;
#pragma unroll 8
    for (int kq = 0; kq < 32; kq++) {
        const int k = kbase + kq;
        const float* mrow = &Ms[k*PADN + ty*8];
        ulonglong2 av0 = *(const ulonglong2*)(mrow);
        ulonglong2 av1 = *(const ulonglong2*)(mrow + 4);
        float4 xv = *(const float4*)&Xs[k*PADN + tx*4];
        u64 gs0 = splat2(xv.x), gs1 = splat2(xv.y), gs2 = splat2(xv.z), gs3 = splat2(xv.w);
        ffma2(acc[0][0], av0.x, gs0); ffma2(acc[0][1], av0.x, gs1);
        ffma2(acc[0][2], av0.x, gs2); ffma2(acc[0][3], av0.x, gs3);
        ffma2(acc[1][0], av0.y, gs0); ffma2(acc[1][1], av0.y, gs1);
        ffma2(acc[1][2], av0.y, gs2); ffma2(acc[1][3], av0.y, gs3);
        ffma2(acc[2][0], av1.x, gs0); ffma2(acc[2][1], av1.x, gs1);
        ffma2(acc[2][2], av1.x, gs2); ffma2(acc[2][3], av1.x, gs3);
        ffma2(acc[3][0], av1.y, gs0); ffma2(acc[3][1], av1.y, gs1);
        ffma2(acc[3][2], av1.y, gs2); ffma2(acc[3][3], av1.y, gs3);
    }
    // merge the two k-halves via smem (Xs is dead; conflict-light layout)
    __syncthreads();
    u64* xred = (u64*)Xs;
    if (wh == 1) {
#pragma unroll
        for (int i = 0; i < 4; i++)
#pragma unroll
            for (int j = 0; j < 4; j++)
                xred[(i*4 + j)*128 + tl] = acc[i][j];
    }
    __syncthreads();
    if (wh == 0) {
#pragma unroll
        for (int i = 0; i < 4; i++)
#pragma unroll
            for (int j = 0; j < 4; j++) {
                float2 o = unpack2(xred[(i*4 + j)*128 + tl]);
                float2 m = unpack2(acc[i][j]);
                acc[i][j] = pack2(m.x + o.x, m.y + o.y);
            }
    }

    float* outb = out + (size_t)b*outBstride + (size_t)z*CC*NN + n0;
    float* outb2 = out2 ? out2 + (size_t)b*outBstride + (size_t)z*CC*NN + n0 : nullptr;
    float4 sc = {1.f,1.f,1.f,1.f};
    if (outb2) {
        sc.x = scInv[tx*4]; sc.y = scInv[tx*4+1];
        sc.z = scInv[tx*4+2]; sc.w = scInv[tx*4+3];
    }
    if (wh == 0) {
        float4 ps1 = {0.f,0.f,0.f,0.f};
        float4 ps2 = {0.f,0.f,0.f,0.f};
#pragma unroll
        for (int i = 0; i < 4; i++) {
            int o = ty*8 + 2*i;
            float b0 = bias ? bias[o]   : 0.f;
            float b1 = bias ? bias[o+1] : 0.f;
            float2 v0 = unpack2(acc[i][0]), v1 = unpack2(acc[i][1]);
            float2 v2 = unpack2(acc[i][2]), v3 = unpack2(acc[i][3]);
            float4 lo = {v0.x + b0, v1.x + b0, v2.x + b0, v3.x + b0};
            float4 hi = {v0.y + b1, v1.y + b1, v2.y + b1, v3.y + b1};
            if (roundOut) {
                lo.x = rnd_tf32(lo.x); lo.y = rnd_tf32(lo.y);
                lo.z = rnd_tf32(lo.z); lo.w = rnd_tf32(lo.w);
                hi.x = rnd_tf32(hi.x); hi.y = rnd_tf32(hi.y);
                hi.z = rnd_tf32(hi.z); hi.w = rnd_tf32(hi.w);
            }
            if (attA) {
                float a1o = a1s[o], a1o1 = a1s[o+1];
                float a2o = a2s[o], a2o1 = a2s[o+1];
                ps1.x = fmaf(lo.x, a1o, fmaf(hi.x, a1o1, ps1.x));
                ps1.y = fmaf(lo.y, a1o, fmaf(hi.y, a1o1, ps1.y));
                ps1.z = fmaf(lo.z, a1o, fmaf(hi.z, a1o1, ps1.z));
                ps1.w = fmaf(lo.w, a1o, fmaf(hi.w, a1o1, ps1.w));
                ps2.x = fmaf(lo.x, a2o, fmaf(hi.x, a2o1, ps2.x));
                ps2.y = fmaf(lo.y, a2o, fmaf(hi.y, a2o1, ps2.y));
                ps2.z = fmaf(lo.z, a2o, fmaf(hi.z, a2o1, ps2.z));
                ps2.w = fmaf(lo.w, a2o, fmaf(hi.w, a2o1, ps2.w));
            }
            if (sqo) {
                ps1.x = fmaf(lo.x, lo.x, fmaf(hi.x, hi.x, ps1.x));
                ps1.y = fmaf(lo.y, lo.y, fmaf(hi.y, hi.y, ps1.y));
                ps1.z = fmaf(lo.z, lo.z, fmaf(hi.z, hi.z, ps1.z));
                ps1.w = fmaf(lo.w, lo.w, fmaf(hi.w, hi.w, ps1.w));
            }
            *(float4*)(outb + (size_t)o*NN + tx*4) = lo;
            *(float4*)(outb + (size_t)(o+1)*NN + tx*4) = hi;
            if (outb2) {
                float4 lo2 = {rnd_tf32(lo.x*sc.x), rnd_tf32(lo.y*sc.y),
                              rnd_tf32(lo.z*sc.z), rnd_tf32(lo.w*sc.w)};
                float4 hi2 = {rnd_tf32(hi.x*sc.x), rnd_tf32(hi.y*sc.y),
                              rnd_tf32(hi.z*sc.z), rnd_tf32(hi.w*sc.w)};
                *(float4*)(outb2 + (size_t)o*NN + tx*4) = lo2;
                *(float4*)(outb2 + (size_t)(o+1)*NN + tx*4) = hi2;
            }
            if (xTo) {
                const float* plo = &lo.x;
                const float* phi = &hi.x;
#pragma unroll
                for (int q = 0; q < 4; q++) {
                    Ms[(tx*4 + q)*PADN + o]   = rnd_tf32(plo[q]);
                    Ms[(tx*4 + q)*PADN + o+1] = rnd_tf32(phi[q]);
                }
            }
        }
        if (attA || sqo) {
            *(float4*)&redA[ty*64 + tx*4] = ps1;
            if (attA) *(float4*)&redB[ty*64 + tx*4] = ps2;
        }
    }
    if (attA || sqo || xTo) __syncthreads();
    if (xTo) {
        // coalesced transposed write with all 256 threads: 16 floats each
        float* xTb = xTo + ((size_t)b*NN + n0) * CC;
        int r = tid >> 2, quarter = tid & 3;
        const float* srow = &Ms[r*PADN + quarter*16];
        float* drow = xTb + (size_t)r*CC + quarter*16;
#pragma unroll
        for (int q = 0; q < 16; q += 4)
            *(float4*)(drow + q) = *(const float4*)(srow + q);
    }
    if ((attA || sqo) && tid < 64) {
        float sa = 0.f, sb = 0.f;
#pragma unroll
        for (int r = 0; r < 8; r++) {
            sa += redA[r*64 + tid];
            if (attA) sb += redB[r*64 + tid];
        }
        if (attA) {
            s1o[b*NN + n0 + tid] = sa;
            s2o[b*NN + n0 + tid] = sb;
        } else {
            sqo[b*NN + n0 + tid] = sa;
        }
    }
}

// ---------------- attention row max + inv-sum ----------------
__global__ void k_attinv() {
    int b = blockIdx.y, t = threadIdx.x;
    const float* s2 = g_s2 + b*NN;
    __shared__ float sh[256];
    float mx = fmaxf(fmaxf(s2[t], s2[t+256]), fmaxf(s2[t+512], s2[t+768]));
    sh[t] = mx; __syncthreads();
    for (int o = 128; o > 0; o >>= 1) { if (t < o) sh[t] = fmaxf(sh[t], sh[t+o]); __syncthreads(); }
    float mxs2 = sh[0];

    int row = blockIdx.x * 8 + (t >> 5);
    int lane = t & 31;
    float s1v = g_s1[b*NN + row];
    float m = s1v + mxs2;
    m = (m > 0.f) ? m : 0.01f * m;
    float sum = 0.f;
    for (int j = lane; j < NN; j += 32) {
        float e = s1v + s2[j];
        e = (e > 0.f) ? e : 0.01f * e;
        sum += __expf(e - m);
    }
#pragma unroll
    for (int o = 16; o > 0; o >>= 1) sum += __shfl_down_sync(0xffffffffu, sum, o);
    if (lane == 0) {
        g_amx [b*NN + row] = m;
        g_ainv[b*NN + row] = 1.f / sum;
    }
}

// ---------------- layernorm stats + final fuse ----------------
__global__ void k_lnstats() {
    int b = blockIdx.x, path = blockIdx.y, t = threadIdx.x;
    size_t base = (size_t)b*(2*CC)*NN + (size_t)path*CC*NN;
    float s = 0.f, ss = 0.f;
    for (int i = t; i < CC*NN; i += 1024) {
        float v = g_sxa[base + i] + g_sxb[base + i];
        s += v; ss = fmaf(v, v, ss);
    }
    __shared__ float shs[1024], shq[1024];
    shs[t] = s; shq[t] = ss; __syncthreads();
    for (int o = 512; o > 0; o >>= 1) {
        if (t < o) { shs[t] += shs[t+o]; shq[t] += shq[t+o]; }
        __syncthreads();
    }
    if (t == 0) {
        float mean = shs[0] * (1.f/65536.f);
        float var  = shq[0] * (1.f/65536.f) - mean*mean;
        g_stats[(path*BB + b)*2 + 0] = mean;
        g_stats[(path*BB + b)*2 + 1] = rsqrtf(var + 1e-5f);
    }
}

__global__ void k_final(const float* __restrict__ ct, const float* __restrict__ ln_w,
                        const float* __restrict__ ln_b, float* __restrict__ out) {
    size_t idx = (size_t)blockIdx.x * 256 + threadIdx.x;
    int b  = (int)(idx / (CC*NN));
    int cn = (int)(idx % (CC*NN));
    float m1 = g_stats[b*2 + 0],            r1 = g_stats[b*2 + 1];
    float m2 = g_stats[(BB + b)*2 + 0],     r2 = g_stats[(BB + b)*2 + 1];
    float w = ln_w[cn], bb = ln_b[cn];
    size_t base = (size_t)b*(2*CC)*NN + cn;
    float z1v = g_sxa[base] + g_sxb[base];
    float z2v = g_sxa[base + (size_t)CC*NN] + g_sxb[base + (size_t)CC*NN];
    float xnew = (z1v - m1) * r1 * w + bb;
    float z2   = (z2v - m2) * r2 * w + bb;
    float ft = 0.5f * z2 * (1.f + erff(z2 * 0.70710678118654752f));
    float ctv = ct[idx];
    float ctn = xnew + ft * (ctv - xnew);
    float el  = (ctn > 0.f) ? ctn : expm1f(ctn);
    float xu  = g_xuai[idx];
    float ht  = xu + ft * (el - xu);
    out[idx] = ht;
    out[(size_t)BB*CC*NN + idx] = ctn;
}

// ---------------- host launch ----------------
struct DevPtrs {
    float *gl, *g1, *g2, *wr, *h0a, *hT, *xuai, *xuaiT;
    float *pa, *pb, *pc, *pd;
    float *l12, *l12s, *t12a, *t12b, *u12, *a12a, *a12b, *sxa, *sxb;
    float *s1, *s2, *sq;
    bool init;
};
static DevPtrs P = {};
static const int GRAM_SMEM = 2 * 128 * GSTRIDE_W * 4;

static void init_ptrs() {
    if (P.init) return;
    void* p;
#define GET(sym, field) cudaGetSymbolAddress(&p, sym); P.field = (float*)p;
    GET(g_gl, gl)   GET(g_g1, g1)   GET(g_g2, g2)
    GET(g_wr, wr)    GET(g_h0a, h0a) GET(g_hT, hT)
    GET(g_xuai, xuai) GET(g_xuaiT, xuaiT)
    GET(g_pa, pa)    GET(g_pb, pb)   GET(g_pc, pc)   GET(g_pd, pd)
    GET(g_l12, l12)  GET(g_l12s, l12s)
    GET(g_t12a, t12a) GET(g_t12b, t12b) GET(g_u12, u12)
    GET(g_a12a, a12a) GET(g_a12b, a12b) GET(g_sxa, sxa) GET(g_sxb, sxb)
    GET(g_s1, s1) GET(g_s2, s2) GET(g_sq, sq)
#undef GET
    cudaFuncSetAttribute(k_gram_mma, cudaFuncAttributeMaxDynamicSharedMemorySize, GRAM_SMEM);
    P.init = true;
}

extern "C" void kernel_launch(void* const* d_in, const int* in_sizes, int n_in,
                              void* d_out, int out_size) {
    const float* x      = (const float*)d_in[0];
    const float* ct     = (const float*)d_in[1];
    const float* graph  = (const float*)d_in[2];
    const float* emb_w  = (const float*)d_in[3];
    const float* emb_b  = (const float*)d_in[4];
    const float* emb2_w = (const float*)d_in[5];
    const float* emb2_b = (const float*)d_in[6];
    const float* att_W  = (const float*)d_in[7];
    const float* att_a  = (const float*)d_in[8];
    // d_in[9] = att_GL : unused (softmax output strictly positive => mask no-op)
    const float* uai_w  = (const float*)d_in[10];
    const float* uai_b  = (const float*)d_in[11];
    const float* lin1_w = (const float*)d_in[12];
    const float* lin2_w = (const float*)d_in[13];
    const float* lin2_b = (const float*)d_in[14];
    const float* ln_w   = (const float*)d_in[15];
    const float* ln_b   = (const float*)d_in[16];
    float* out = (float*)d_out;

    init_ptrs();

    const size_t GLSTRIDE = (size_t)NN * NN;
    const size_t SB = (size_t)CC * NN;
    const size_t DB = (size_t)2 * CC * NN;
    const dim3 gridC1(NN/64, BB, 1);
    const dim3 gridC2(NN/64, BB, 2);

    // laplacian d, then combined prep (lapT + wround + emb1)
    k_lap_d<<<dim3(NN, 2), 256>>>(graph);
    k_prep <<<dim3(1024, 4), 256>>>(graph, emb2_w, x, emb_w, emb_b);

    // embedding GEMM
    mma_gemm<<<dim3(8, BB/2, 4), 256>>>(P.h0a, DB, 128, P.wr, 0, 4,
                                        nullptr, nullptr, emb2_b,
                                        P.pa, P.pb, P.pc, P.pd, DB);

    // attention: hT chanmix with fused s1/s2 rank-1 scores
    chanmixD<<<gridC1, 256>>>(P.pa, P.pb, P.pc, P.pd, 0, SB, 0,
                              att_W, nullptr, att_W, nullptr, 1, 1, P.hT, SB,
                              nullptr, 0, att_a, P.s1, P.s2, nullptr, nullptr);
    k_attinv<<<dim3(NN/8, BB), 256>>>();
    mma_gemm_att<<<dim3(8, BB, 2), 256>>>(P.hT, SB, P.pa, P.pb, SB);

    // UAI chanmix with fused sumsq + coalesced transposed/rounded copy for gram
    chanmixD<<<gridC1, 256>>>(P.pa, P.pb, nullptr, nullptr, 1, SB, 0,
                              uai_w, uai_b, uai_w, uai_b, 0, 0, P.xuai, SB,
                              nullptr, 0, nullptr, nullptr, nullptr, P.sq, P.xuaiT);

    // learned adjacency: tensor-core gram + fused row partials
    k_gram_mma<<<dim3(8, 8, BB), 256, GRAM_SMEM>>>();

    // l1/l2 stacked propagation; rsinv derived from g_part in-block
    chanmixD<<<gridC2, 256>>>(P.xuai, nullptr, nullptr, nullptr, 0, SB, 0,
                              lin1_w, nullptr, lin2_w, lin2_b, 0, 1, P.l12, DB,
                              P.l12s, 1, nullptr, nullptr, nullptr, nullptr, nullptr);

    // merged: unit0 l12s@gl -> a12a/b ; unit1 l12@g1 -> t12a/b
    mma_gemm2<<<dim3(8, BB, 4), 256>>>(P.l12s, P.gl, GLSTRIDE,
                                       P.l12, P.g1, 0,
                                       P.a12a, P.a12b, P.t12a, P.t12b, DB);

    chanmixD<<<gridC2, 256>>>(P.t12a, P.t12b, nullptr, nullptr, 0, DB, SB,
                              lin1_w, nullptr, lin2_w, lin2_b, 0, 1, P.u12, DB,
                              nullptr, 0, nullptr, nullptr, nullptr, nullptr, nullptr);

    mma_gemm<<<dim3(8, BB, 2), 256>>>(P.u12, DB, 128, P.g2, 0, 2,
                                      P.a12a, P.a12b, nullptr,
                                      P.sxa, P.sxb, nullptr, nullptr, DB);

    // layernorm + gates + output
    k_lnstats<<<dim3(BB, 2), 1024>>>();
    k_final  <<<(BB*CC*NN)/256, 256>>>(ct, ln_w, ln_b, out);
}

// round 16
// speedup vs baseline: 1.0370x; 1.0370x over previous
#include <cuda_runtime.h>
#include <math.h>
#include <stdint.h>

#define BB 16
#define NN 1024
#define CC 64
#define CIN 16
#define PADN 68

typedef unsigned long long u64;

// ---------------- fp32x2 helpers (chanmix) ----------------
__device__ __forceinline__ u64 splat2(float v) {
    u64 r; asm("mov.b64 %0, {%1, %1};" : "=l"(r) : "f"(v)); return r;
}
__device__ __forceinline__ void ffma2(u64& d, u64 a, u64 b) {
    asm("fma.rn.f32x2 %0, %1, %2, %0;" : "+l"(d) : "l"(a), "l"(b));
}
__device__ __forceinline__ float2 unpack2(u64 v) {
    float2 r; asm("mov.b64 {%0, %1}, %2;" : "=f"(r.x), "=f"(r.y) : "l"(v)); return r;
}

// ---------------- mma.sync tf32 + cp.async helpers ----------------
__device__ __forceinline__ uint32_t smem_u32(const void* p) {
    uint32_t a;
    asm("{ .reg .u64 t; cvta.to.shared.u64 t, %1; cvt.u32.u64 %0, t; }" : "=r"(a) : "l"(p));
    return a;
}
__device__ __forceinline__ float rnd_tf32(float f) {
    uint32_t r; asm("cvt.rna.tf32.f32 %0, %1;" : "=r"(r) : "f"(f));
    return __uint_as_float(r);
}
#define LDSM4(r0, r1, r2, r3, addr)                                            \
    asm volatile("ldmatrix.sync.aligned.m8n8.x4.shared.b16 {%0,%1,%2,%3}, [%4];" \
        : "=r"(r0), "=r"(r1), "=r"(r2), "=r"(r3) : "r"(addr))
#define MMA_TF32(c, a0, a1, a2, a3, b0, b1)                                    \
    asm volatile("mma.sync.aligned.m16n8k8.row.col.f32.tf32.tf32.f32 "         \
        "{%0,%1,%2,%3}, {%4,%5,%6,%7}, {%8,%9}, {%0,%1,%2,%3};"                \
        : "+f"((c)[0]), "+f"((c)[1]), "+f"((c)[2]), "+f"((c)[3])               \
        : "r"(a0), "r"(a1), "r"(a2), "r"(a3), "r"(b0), "r"(b1))
__device__ __forceinline__ void cp16(uint32_t dst, const void* src) {
    asm volatile("cp.async.cg.shared.global [%0], [%1], 16;" :: "r"(dst), "l"(src));
}
#define CP_COMMIT()  asm volatile("cp.async.commit_group;" ::: "memory")
#define CP_WAIT1()   asm volatile("cp.async.wait_group 1;" ::: "memory")
#define CP_WAIT0()   asm volatile("cp.async.wait_group 0;" ::: "memory")

// ---------------- static device scratch ----------------
__device__ float g_gl  [BB*NN*NN];
__device__ float g_g1  [NN*NN];
__device__ float g_g2  [NN*NN];
__device__ float g_wr  [NN*NN];
__device__ float g_d   [2*NN];
__device__ float g_h0a [BB*CC*NN];
__device__ float g_hT  [BB*CC*NN];
__device__ float g_xuai[BB*CC*NN];
__device__ float g_xuaiT[BB*NN*CC];
__device__ float g_pa  [BB*CC*NN];
__device__ float g_pb  [BB*CC*NN];
__device__ float g_pc  [BB*CC*NN];
__device__ float g_pd  [BB*CC*NN];
__device__ float g_l12 [BB*2*CC*NN];
__device__ float g_l12s[BB*2*CC*NN];
__device__ float g_t12a[BB*2*CC*NN];
__device__ float g_t12b[BB*2*CC*NN];
__device__ float g_u12 [BB*2*CC*NN];
__device__ float g_a12a[BB*2*CC*NN];
__device__ float g_a12b[BB*2*CC*NN];
__device__ float g_sxa [BB*2*CC*NN];
__device__ float g_sxb [BB*2*CC*NN];
__device__ float g_s1  [BB*NN];
__device__ float g_s2  [BB*NN];
__device__ float g_amx [BB*NN];
__device__ float g_ainv[BB*NN];
__device__ float g_sq  [BB*NN];
__device__ float g_part[BB*8*NN];
__device__ float g_stats[2*BB*2];

#define TPAD 20
#define BUFSTRIDE (128*TPAD*4)

// =========================================================================
// mma_gemm (tf32, 2-stage cp.async): C_ks[b,c,n] = sum_{k in split} A*B
// =========================================================================
__global__ void __launch_bounds__(256, 2)
mma_gemm(const float* __restrict__ A, size_t aBatch, int mvalid,
         const float* __restrict__ B, size_t bBatch, int nsplit,
         const float* __restrict__ add0, const float* __restrict__ add1,
         const float* __restrict__ biasN,
         float* __restrict__ C0, float* __restrict__ C1,
         float* __restrict__ C2, float* __restrict__ C3, size_t cBatch)
{
    __shared__ uint32_t As[2][128*TPAD];
    __shared__ uint32_t Bs[2][128*TPAD];

    const int tid  = threadIdx.x;
    const int lane = tid & 31;
    const int wid  = tid >> 5;
    const int bidx = blockIdx.y;
    const int n0   = blockIdx.x * 128;
    const int ks   = blockIdx.z;
    const int kPer = NN / nsplit;
    const int T    = kPer / 16;
    const int k0b  = ks * kPer;

    const float* Ab = A + (size_t)bidx * aBatch + k0b;
    const float* Bb = B + (size_t)bidx * bBatch + (size_t)n0 * NN + k0b;

    const int frow0 = tid >> 2;
    const int frow1 = 64 + (tid >> 2);
    const int fkq   = (tid & 3) * 4;

    const float* aP0 = Ab + (size_t)frow0 * NN + fkq;
    const float* aP1 = Ab + (size_t)((frow1 < mvalid) ? frow1 : 0) * NN + fkq;
    const float* bP0 = Bb + (size_t)frow0 * NN + fkq;
    const float* bP1 = Bb + (size_t)frow1 * NN + fkq;

    const uint32_t aSm = smem_u32(&As[0][0]);
    const uint32_t bSm = smem_u32(&Bs[0][0]);
    const uint32_t aFill  = aSm + (frow0*TPAD + fkq) * 4;
    const uint32_t aFill1 = aSm + (frow1*TPAD + fkq) * 4;
    const uint32_t bFill  = bSm + (frow0*TPAD + fkq) * 4;
    const uint32_t bFill1 = bSm + (frow1*TPAD + fkq) * 4;

    const int aRowOff = (lane & 15) * TPAD + (lane >> 4) * 4;
    const int bRowOff = ((lane >> 4) * 8 + (lane & 7)) * TPAD + ((lane >> 3) & 1) * 4;

    const int mbase = (wid >> 2) * 64;
    const int nbase = (wid & 3) * 32;

    float c[4][4][4];
#pragma unroll
    for (int i = 0; i < 4; i++)
#pragma unroll
        for (int j = 0; j < 4; j++)
#pragma unroll
            for (int q = 0; q < 4; q++) c[i][j][q] = 0.f;

    cp16(aFill,  aP0); cp16(aFill1, aP1);
    cp16(bFill,  bP0); cp16(bFill1, bP1);
    CP_COMMIT();

    for (int t = 0; t < T; ++t) {
        const int cur = t & 1;
        if (t + 1 < T) {
            const uint32_t off = (uint32_t)((t+1) & 1) * BUFSTRIDE;
            const int ko = (t + 1) * 16;
            cp16(aFill  + off, aP0 + ko);
            cp16(aFill1 + off, aP1 + ko);
            cp16(bFill  + off, bP0 + ko);
            cp16(bFill1 + off, bP1 + ko);
            CP_COMMIT();
            CP_WAIT1();
        } else {
            CP_WAIT0();
        }
        __syncthreads();
        {
            const uint32_t aCur = aSm + cur * BUFSTRIDE;
            const uint32_t bCur = bSm + cur * BUFSTRIDE;
#pragma unroll
            for (int kk = 0; kk < 16; kk += 8) {
                uint32_t a[4][4];
#pragma unroll
                for (int mt = 0; mt < 4; mt++) {
                    uint32_t addr = aCur + ((mbase + mt*16)*TPAD + aRowOff + kk) * 4;
                    LDSM4(a[mt][0], a[mt][1], a[mt][2], a[mt][3], addr);
                }
                uint32_t bfr[4][2];
#pragma unroll
                for (int np = 0; np < 2; np++) {
                    uint32_t addr = bCur + ((nbase + np*16)*TPAD + bRowOff + kk) * 4;
                    LDSM4(bfr[np*2][0], bfr[np*2][1], bfr[np*2+1][0], bfr[np*2+1][1], addr);
                }
#pragma unroll
                for (int mt = 0; mt < 4; mt++)
#pragma unroll
                    for (int nt = 0; nt < 4; nt++)
                        MMA_TF32(c[mt][nt], a[mt][0], a[mt][1], a[mt][2], a[mt][3],
                                 bfr[nt][0], bfr[nt][1]);
            }
        }
        __syncthreads();
    }

    if (mbase >= mvalid) return;
    float* C = (ks == 0) ? C0 : (ks == 1) ? C1 : (ks == 2) ? C2 : C3;
    const float* add = (ks == 0) ? add0 : (ks == 1) ? add1 : nullptr;
    float* Cb = C + (size_t)bidx * cBatch;
    const float* Adb = add ? add + (size_t)bidx * cBatch : nullptr;
    const int gid = lane >> 2, tq = lane & 3;
#pragma unroll
    for (int mt = 0; mt < 4; mt++) {
        const int r = mbase + mt*16 + gid;
#pragma unroll
        for (int nt = 0; nt < 4; nt++) {
            const int col = n0 + nbase + nt*8 + tq*2;
            float2 v0 = { c[mt][nt][0], c[mt][nt][1] };
            float2 v1 = { c[mt][nt][2], c[mt][nt][3] };
            if (biasN && ks == 0) {
                float b0 = biasN[col], b1 = biasN[col+1];
                v0.x += b0; v0.y += b1; v1.x += b0; v1.y += b1;
            }
            if (Adb) {
                float2 d0 = *(const float2*)(Adb + (size_t)r * NN + col);
                float2 d1 = *(const float2*)(Adb + (size_t)(r+8) * NN + col);
                v0.x += d0.x; v0.y += d0.y; v1.x += d1.x; v1.y += d1.y;
            }
            *(float2*)(Cb + (size_t)r * NN + col)     = v0;
            *(float2*)(Cb + (size_t)(r+8) * NN + col) = v1;
        }
    }
}

// =========================================================================
// mma_gemm2 (2-stage): two independent GEMM units (unit = z>>1, ks = z&1).
// =========================================================================
__global__ void __launch_bounds__(256, 2)
mma_gemm2(const float* __restrict__ A0, const float* __restrict__ B0, size_t bS0,
          const float* __restrict__ A1, const float* __restrict__ B1, size_t bS1,
          float* __restrict__ C00, float* __restrict__ C01,
          float* __restrict__ C10, float* __restrict__ C11, size_t cBatch)
{
    __shared__ uint32_t As[2][128*TPAD];
    __shared__ uint32_t Bs[2][128*TPAD];

    const int tid  = threadIdx.x;
    const int lane = tid & 31;
    const int wid  = tid >> 5;
    const int bidx = blockIdx.y;
    const int n0   = blockIdx.x * 128;
    const int unit = blockIdx.z >> 1;
    const int ks   = blockIdx.z & 1;
    const int k0b  = ks * 512;
    const int T    = 32;

    const float* A = unit ? A1 : A0;
    const float* B = unit ? B1 : B0;
    const size_t bBatch = unit ? bS1 : bS0;

    const float* Ab = A + (size_t)bidx * (size_t)(2*CC)*NN + k0b;
    const float* Bb = B + (size_t)bidx * bBatch + (size_t)n0 * NN + k0b;

    const int frow0 = tid >> 2;
    const int frow1 = 64 + (tid >> 2);
    const int fkq   = (tid & 3) * 4;

    const float* aP0 = Ab + (size_t)frow0 * NN + fkq;
    const float* aP1 = Ab + (size_t)frow1 * NN + fkq;
    const float* bP0 = Bb + (size_t)frow0 * NN + fkq;
    const float* bP1 = Bb + (size_t)frow1 * NN + fkq;

    const uint32_t aSm = smem_u32(&As[0][0]);
    const uint32_t bSm = smem_u32(&Bs[0][0]);
    const uint32_t aFill  = aSm + (frow0*TPAD + fkq) * 4;
    const uint32_t aFill1 = aSm + (frow1*TPAD + fkq) * 4;
    const uint32_t bFill  = bSm + (frow0*TPAD + fkq) * 4;
    const uint32_t bFill1 = bSm + (frow1*TPAD + fkq) * 4;

    const int aRowOff = (lane & 15) * TPAD + (lane >> 4) * 4;
    const int bRowOff = ((lane >> 4) * 8 + (lane & 7)) * TPAD + ((lane >> 3) & 1) * 4;

    const int mbase = (wid >> 2) * 64;
    const int nbase = (wid & 3) * 32;

    float c[4][4][4];
#pragma unroll
    for (int i = 0; i < 4; i++)
#pragma unroll
        for (int j = 0; j < 4; j++)
#pragma unroll
            for (int q = 0; q < 4; q++) c[i][j][q] = 0.f;

    cp16(aFill,  aP0); cp16(aFill1, aP1);
    cp16(bFill,  bP0); cp16(bFill1, bP1);
    CP_COMMIT();

    for (int t = 0; t < T; ++t) {
        const int cur = t & 1;
        if (t + 1 < T) {
            const uint32_t off = (uint32_t)((t+1) & 1) * BUFSTRIDE;
            const int ko = (t + 1) * 16;
            cp16(aFill  + off, aP0 + ko);
            cp16(aFill1 + off, aP1 + ko);
            cp16(bFill  + off, bP0 + ko);
            cp16(bFill1 + off, bP1 + ko);
            CP_COMMIT();
            CP_WAIT1();
        } else {
            CP_WAIT0();
        }
        __syncthreads();
        {
            const uint32_t aCur = aSm + cur * BUFSTRIDE;
            const uint32_t bCur = bSm + cur * BUFSTRIDE;
#pragma unroll
            for (int kk = 0; kk < 16; kk += 8) {
                uint32_t a[4][4];
#pragma unroll
                for (int mt = 0; mt < 4; mt++) {
                    uint32_t addr = aCur + ((mbase + mt*16)*TPAD + aRowOff + kk) * 4;
                    LDSM4(a[mt][0], a[mt][1], a[mt][2], a[mt][3], addr);
                }
                uint32_t bfr[4][2];
#pragma unroll
                for (int np = 0; np < 2; np++) {
                    uint32_t addr = bCur + ((nbase + np*16)*TPAD + bRowOff + kk) * 4;
                    LDSM4(bfr[np*2][0], bfr[np*2][1], bfr[np*2+1][0], bfr[np*2+1][1], addr);
                }
#pragma unroll
                for (int mt = 0; mt < 4; mt++)
#pragma unroll
                    for (int nt = 0; nt < 4; nt++)
                        MMA_TF32(c[mt][nt], a[mt][0], a[mt][1], a[mt][2], a[mt][3],
                                 bfr[nt][0], bfr[nt][1]);
            }
        }
        __syncthreads();
    }

    float* C = unit ? (ks ? C11 : C10) : (ks ? C01 : C00);
    float* Cb = C + (size_t)bidx * cBatch;
    const int gid = lane >> 2, tq = lane & 3;
#pragma unroll
    for (int mt = 0; mt < 4; mt++) {
        const int r = mbase + mt*16 + gid;
#pragma unroll
        for (int nt = 0; nt < 4; nt++) {
            const int col = n0 + nbase + nt*8 + tq*2;
            float2 v0 = { c[mt][nt][0], c[mt][nt][1] };
            float2 v1 = { c[mt][nt][2], c[mt][nt][3] };
            *(float2*)(Cb + (size_t)r * NN + col)     = v0;
            *(float2*)(Cb + (size_t)(r+8) * NN + col) = v1;
        }
    }
}

// =========================================================================
// mma_gemm_att: attention MMA with on-the-fly B generation (2-stage).
// =========================================================================
__device__ __forceinline__ float attval(float s1v, float s2v, float m, float iv) {
    float e = s1v + s2v;
    e = (e > 0.f) ? e : 0.01f * e;
    return rnd_tf32(__expf(e - m) * iv);
}

__global__ void __launch_bounds__(256, 2)
mma_gemm_att(const float* __restrict__ A, size_t aBatch,
             float* __restrict__ C0, float* __restrict__ C1, size_t cBatch)
{
    __shared__ uint32_t As[2][128*TPAD];
    __shared__ float    Bs[2][128*TPAD];

    const int tid  = threadIdx.x;
    const int lane = tid & 31;
    const int wid  = tid >> 5;
    const int bidx = blockIdx.y;
    const int n0   = blockIdx.x * 128;
    const int ks   = blockIdx.z;
    const int k0b  = ks * 512;
    const int T    = 32;

    const float* Ab = A + (size_t)bidx * aBatch + k0b;

    const int frow0 = tid >> 2;
    const int frow1 = 64 + (tid >> 2);
    const int fkq   = (tid & 3) * 4;

    const float* aP0 = Ab + (size_t)frow0 * NN + fkq;
    const float* aP1 = Ab;

    const float s1v0 = g_s1 [bidx*NN + n0 + frow0];
    const float m0   = g_amx[bidx*NN + n0 + frow0];
    const float iv0  = g_ainv[bidx*NN + n0 + frow0];
    const float s1v1 = g_s1 [bidx*NN + n0 + frow1];
    const float m1   = g_amx[bidx*NN + n0 + frow1];
    const float iv1  = g_ainv[bidx*NN + n0 + frow1];
    const float* s2p = g_s2 + bidx*NN + k0b + fkq;

    const uint32_t aSm = smem_u32(&As[0][0]);
    const uint32_t bSm = smem_u32(&Bs[0][0]);
    const uint32_t aFill  = aSm + (frow0*TPAD + fkq) * 4;
    const uint32_t aFill1 = aSm + (frow1*TPAD + fkq) * 4;

    const int aRowOff = (lane & 15) * TPAD + (lane >> 4) * 4;
    const int bRowOff = ((lane >> 4) * 8 + (lane & 7)) * TPAD + ((lane >> 3) & 1) * 4;

    const int mbase = (wid >> 2) * 64;
    const int nbase = (wid & 3) * 32;

    float c[4][4][4];
#pragma unroll
    for (int i = 0; i < 4; i++)
#pragma unroll
        for (int j = 0; j < 4; j++)
#pragma unroll
            for (int q = 0; q < 4; q++) c[i][j][q] = 0.f;

    cp16(aFill,  aP0); cp16(aFill1, aP1 + fkq);
    CP_COMMIT();
    {
        float4 s2v = *(const float4*)(s2p);
        float4 b0 = { attval(s1v0, s2v.x, m0, iv0), attval(s1v0, s2v.y, m0, iv0),
                      attval(s1v0, s2v.z, m0, iv0), attval(s1v0, s2v.w, m0, iv0) };
        float4 b1 = { attval(s1v1, s2v.x, m1, iv1), attval(s1v1, s2v.y, m1, iv1),
                      attval(s1v1, s2v.z, m1, iv1), attval(s1v1, s2v.w, m1, iv1) };
        *(float4*)&Bs[0][frow0*TPAD + fkq] = b0;
        *(float4*)&Bs[0][frow1*TPAD + fkq] = b1;
    }
    __syncthreads();

    for (int t = 0; t < T; ++t) {
        const int cur = t & 1;
        if (t + 1 < T) {
            const int nxt = (t+1) & 1;
            const uint32_t off = (uint32_t)nxt * BUFSTRIDE;
            const int ko = (t + 1) * 16;
            cp16(aFill  + off, aP0 + ko);
            cp16(aFill1 + off, aP1 + ko + fkq);
            CP_COMMIT();
            float4 s2v = *(const float4*)(s2p + ko);
            float4 b0 = { attval(s1v0, s2v.x, m0, iv0), attval(s1v0, s2v.y, m0, iv0),
                          attval(s1v0, s2v.z, m0, iv0), attval(s1v0, s2v.w, m0, iv0) };
            float4 b1 = { attval(s1v1, s2v.x, m1, iv1), attval(s1v1, s2v.y, m1, iv1),
                          attval(s1v1, s2v.z, m1, iv1), attval(s1v1, s2v.w, m1, iv1) };
            *(float4*)&Bs[nxt][frow0*TPAD + fkq] = b0;
            *(float4*)&Bs[nxt][frow1*TPAD + fkq] = b1;
            CP_WAIT1();
        } else {
            CP_WAIT0();
        }
        __syncthreads();
        {
            const uint32_t aCur = aSm + cur * BUFSTRIDE;
            const uint32_t bCur = bSm + cur * BUFSTRIDE;
#pragma unroll
            for (int kk = 0; kk < 16; kk += 8) {
                uint32_t a[4][4];
#pragma unroll
                for (int mt = 0; mt < 4; mt++) {
                    uint32_t addr = aCur + ((mbase + mt*16)*TPAD + aRowOff + kk) * 4;
                    LDSM4(a[mt][0], a[mt][1], a[mt][2], a[mt][3], addr);
                }
                uint32_t bfr[4][2];
#pragma unroll
                for (int np = 0; np < 2; np++) {
                    uint32_t addr = bCur + ((nbase + np*16)*TPAD + bRowOff + kk) * 4;
                    LDSM4(bfr[np*2][0], bfr[np*2][1], bfr[np*2+1][0], bfr[np*2+1][1], addr);
                }
#pragma unroll
                for (int mt = 0; mt < 4; mt++)
#pragma unroll
                    for (int nt = 0; nt < 4; nt++)
                        MMA_TF32(c[mt][nt], a[mt][0], a[mt][1], a[mt][2], a[mt][3],
                                 bfr[nt][0], bfr[nt][1]);
            }
        }
        __syncthreads();
    }

    if (mbase >= 64) return;
    float* Cb = (ks ? C1 : C0) + (size_t)bidx * cBatch;
    const int gid = lane >> 2, tq = lane & 3;
#pragma unroll
    for (int mt = 0; mt < 4; mt++) {
        const int r = mbase + mt*16 + gid;
#pragma unroll
        for (int nt = 0; nt < 4; nt++) {
            const int col = n0 + nbase + nt*8 + tq*2;
            float2 v0 = { c[mt][nt][0], c[mt][nt][1] };
            float2 v1 = { c[mt][nt][2], c[mt][nt][3] };
            *(float2*)(Cb + (size_t)r * NN + col)     = v0;
            *(float2*)(Cb + (size_t)(r+8) * NN + col) = v1;
        }
    }
}

// =========================================================================
// k_gram_mma: gl = transform( XtT @ XtT^T ), row partial sums fused.
// =========================================================================
#define GSTRIDE_W 68
__global__ void __launch_bounds__(256)
k_gram_mma()
{
    extern __shared__ uint32_t gsm[];
    __shared__ float rowsW[8][64];

    const int tid  = threadIdx.x;
    const int lane = tid & 31;
    const int wid  = tid >> 5;
    const int b  = blockIdx.z;
    const int i0 = blockIdx.x * 128;
    const int jb = blockIdx.y;
    const int j0 = jb * 128;

    const float* XT = g_xuaiT + (size_t)b * NN * CC;
    const uint32_t aSm = smem_u32(&gsm[0]);
    const uint32_t bSm = aSm + 128*GSTRIDE_W*4;

#pragma unroll
    for (int q = 0; q < 8; q++) {
        int f = q * 256 + tid;
        int row = f >> 4, seg = (f & 15) * 4;
        cp16(aSm + (row*GSTRIDE_W + seg) * 4, XT + (size_t)(i0 + row) * CC + seg);
        cp16(bSm + (row*GSTRIDE_W + seg) * 4, XT + (size_t)(j0 + row) * CC + seg);
    }
    CP_COMMIT();
    CP_WAIT0();
    __syncthreads();

    const int aRowOff = (lane & 15) * GSTRIDE_W + (lane >> 4) * 4;
    const int bRowOff = ((lane >> 4) * 8 + (lane & 7)) * GSTRIDE_W + ((lane >> 3) & 1) * 4;
    const int mbase = (wid >> 2) * 64;
    const int nbase = (wid & 3) * 32;

    float c[4][4][4];
#pragma unroll
    for (int i = 0; i < 4; i++)
#pragma unroll
        for (int j = 0; j < 4; j++)
#pragma unroll
            for (int q = 0; q < 4; q++) c[i][j][q] = 0.f;

#pragma unroll
    for (int kk = 0; kk < 64; kk += 8) {
        uint32_t a[4][4];
#pragma unroll
        for (int mt = 0; mt < 4; mt++) {
            uint32_t addr = aSm + ((mbase + mt*16)*GSTRIDE_W + aRowOff + kk) * 4;
            LDSM4(a[mt][0], a[mt][1], a[mt][2], a[mt][3], addr);
        }
        uint32_t bfr[4][2];
#pragma unroll
        for (int np = 0; np < 2; np++) {
            uint32_t addr = bSm + ((nbase + np*16)*GSTRIDE_W + bRowOff + kk) * 4;
            LDSM4(bfr[np*2][0], bfr[np*2][1], bfr[np*2+1][0], bfr[np*2+1][1], addr);
        }
#pragma unroll
        for (int mt = 0; mt < 4; mt++)
#pragma unroll
            for (int nt = 0; nt < 4; nt++)
                MMA_TF32(c[mt][nt], a[mt][0], a[mt][1], a[mt][2], a[mt][3],
                         bfr[nt][0], bfr[nt][1]);
    }

    const float* sq = g_sq + b*NN;
    float* glb = g_gl + (size_t)b*NN*NN;
    const int gid = lane >> 2, tq = lane & 3;
#pragma unroll
    for (int mt = 0; mt < 4; mt++) {
        const int rl = mbase + mt*16 + gid;
        const int gi0 = i0 + rl, gi1 = gi0 + 8;
        const float sqa = sq[gi0], sqb = sq[gi1];
        float rp0 = 0.f, rp1 = 0.f;
#pragma unroll
        for (int nt = 0; nt < 4; nt++) {
            const int col = j0 + nbase + nt*8 + tq*2;
            const float sj0 = sq[col], sj1 = sq[col+1];
            float d00 = fmaxf(sqa + sj0 - 2.f*c[mt][nt][0], 0.f);
            float d01 = fmaxf(sqa + sj1 - 2.f*c[mt][nt][1], 0.f);
            float d10 = fmaxf(sqb + sj0 - 2.f*c[mt][nt][2], 0.f);
            float d11 = fmaxf(sqb + sj1 - 2.f*c[mt][nt][3], 0.f);
            float v00 = rnd_tf32(__expf(__expf(-d00*(1.f/128.f)) + ((gi0 == col)   ? 1.f : 0.f)));
            float v01 = rnd_tf32(__expf(__expf(-d01*(1.f/128.f)) + ((gi0 == col+1) ? 1.f : 0.f)));
            float v10 = rnd_tf32(__expf(__expf(-d10*(1.f/128.f)) + ((gi1 == col)   ? 1.f : 0.f)));
            float v11 = rnd_tf32(__expf(__expf(-d11*(1.f/128.f)) + ((gi1 == col+1) ? 1.f : 0.f)));
            float2 w0 = {v00, v01}, w1 = {v10, v11};
            *(float2*)(glb + (size_t)gi0 * NN + col) = w0;
            *(float2*)(glb + (size_t)gi1 * NN + col) = w1;
            rp0 += v00 + v01;
            rp1 += v10 + v11;
        }
        rp0 += __shfl_xor_sync(0xffffffffu, rp0, 1, 4);
        rp0 += __shfl_xor_sync(0xffffffffu, rp0, 2, 4);
        rp1 += __shfl_xor_sync(0xffffffffu, rp1, 1, 4);
        rp1 += __shfl_xor_sync(0xffffffffu, rp1, 2, 4);
        if (tq == 0) {
            rowsW[wid][mt*16 + gid]     = rp0;
            rowsW[wid][mt*16 + gid + 8] = rp1;
        }
    }
    __syncthreads();
    if (tid < 128) {
        int half = tid >> 6, lr = tid & 63;
        float s = rowsW[half*4 + 0][lr] + rowsW[half*4 + 1][lr]
                + rowsW[half*4 + 2][lr] + rowsW[half*4 + 3][lr];
        g_part[((size_t)b*8 + jb)*NN + i0 + tid] = s;
    }
}

// ---------------- k_prep: lapT (y=0,1) + wround (y=2) + emb1 (y=3) ----------------
__global__ void k_prep(const float* __restrict__ graph, const float* __restrict__ emb2_w,
                       const float* __restrict__ x, const float* __restrict__ emb_w,
                       const float* __restrict__ emb_b) {
    __shared__ float w[CC*CIN];
    __shared__ float bsm[CC];
    const int plane = blockIdx.y;
    const int t = threadIdx.x;
    if (plane < 2) {
        int kg = plane, m = blockIdx.x;
        const float* src = graph + (size_t)kg*NN*NN + (size_t)m*NN;
        float* dst = ((kg == 0) ? g_g1 : g_g2) + (size_t)m*NN;
        const float* d = g_d + kg*NN;
        float dm = d[m];
#pragma unroll
        for (int q = 0; q < 4; q++) {
            int k = t + 256*q;
            float v = src[k] + ((m == k) ? 1.f : 0.f);
            dst[k] = rnd_tf32(v * dm * d[k]);
        }
    } else if (plane == 2) {
        size_t i = ((size_t)blockIdx.x * 256 + t) * 4;
        float4 v = *(const float4*)(emb2_w + i);
        float4 ww = { rnd_tf32(v.x), rnd_tf32(v.y), rnd_tf32(v.z), rnd_tf32(v.w) };
        *(float4*)(g_wr + i) = ww;
    } else {
        for (int i = t; i < CC*CIN; i += 256) w[i] = emb_w[i];
        if (t < CC) bsm[t] = emb_b[t];
        __syncthreads();
        int idx = blockIdx.x;
        int b = idx & 15;
        int n = ((idx >> 4) & 3) * 256 + t;
        int e0 = (idx >> 6) * 4;
        float xv[CIN];
        const float* xp = x + (size_t)b*CIN*NN + n;
#pragma unroll
        for (int c = 0; c < CIN; c++) xv[c] = xp[(size_t)c*NN];
        float* out = g_h0a + (size_t)b*CC*NN + n;
#pragma unroll
        for (int e = e0; e < e0 + 4; e++) {
            float s = bsm[e];
#pragma unroll
            for (int c = 0; c < CIN; c++) s = fmaf(w[e*CIN + c], xv[c], s);
            float lv = (s > 0.f) ? s : 0.01f*s;
            out[(size_t)e*NN] = rnd_tf32(lv);
        }
    }
}

// ---------------- laplacian d ----------------
__global__ void k_lap_d(const float* __restrict__ graph) {
    int i = blockIdx.x, k = blockIdx.y, t = threadIdx.x;
    const float* row = graph + (size_t)k*NN*NN + (size_t)i*NN;
    float s = 0.f;
    for (int j = t; j < NN; j += 256) s += row[j];
    __shared__ float sh[256];
    sh[t] = s; __syncthreads();
    for (int o = 128; o > 0; o >>= 1) { if (t < o) sh[t] += sh[t+o]; __syncthreads(); }
    if (t == 0) g_d[k*NN + i] = rsqrtf(sh[0] + 1.0f);
}

// ------- 64x64 channel mix (128 threads); optional fused s1/s2, sq,
//         coalesced smem-staged transposed output, 2nd scaled output -------
__global__ void __launch_bounds__(128)
chanmixD(const float* __restrict__ in, const float* __restrict__ in2,
         const float* __restrict__ in3, const float* __restrict__ in4,
         int reluIn, size_t inBstride, size_t inZoff,
         const float* __restrict__ Wa, const float* __restrict__ ba,
         const float* __restrict__ Wb, const float* __restrict__ bb_,
         int trans, int roundOut, float* __restrict__ out, size_t outBstride,
         float* __restrict__ out2, int scaleFromPart,
         const float* __restrict__ attA, float* __restrict__ s1o,
         float* __restrict__ s2o, float* __restrict__ sqo,
         float* __restrict__ xTo) {
    const int z = blockIdx.z;
    const float* W    = z ? Wb  : Wa;
    const float* bias = z ? bb_ : ba;
    const int b = blockIdx.y, n0 = blockIdx.x * 64;
    __shared__ float Ms[64*PADN];
    __shared__ float Xs[64*PADN];
    __shared__ float redA[8*64];
    __shared__ float redB[8*64];
    __shared__ float a1s[64], a2s[64];
    __shared__ float scInv[64];
    const int tid = threadIdx.x;
    for (int i = tid; i < 64*64; i += 128) {
        int o = i >> 6, k = i & 63;
        Ms[k*PADN + o] = trans ? W[k*64 + o] : W[o*64 + k];
    }
    if (attA) {
        if (tid < 64) a1s[tid] = attA[tid];
        else a2s[tid-64] = attA[tid];
    }
    if (scaleFromPart && tid < 64) {
        float s = 0.f;
#pragma unroll
        for (int j = 0; j < 8; j++) s += g_part[((size_t)b*8 + j)*NN + n0 + tid];
        scInv[tid] = 1.f / s;
    }
    const size_t boff = (size_t)b*inBstride + (size_t)z*inZoff + n0;
    for (int i = tid; i < 64*16; i += 128) {
        int k = i >> 4, n4 = (i & 15) * 4;
        size_t off = boff + (size_t)k*NN + n4;
        float4 v = *(const float4*)(in + off);
        if (in2) { float4 w2 = *(const float4*)(in2 + off); v.x+=w2.x; v.y+=w2.y; v.z+=w2.z; v.w+=w2.w; }
        if (in3) { float4 w3 = *(const float4*)(in3 + off); v.x+=w3.x; v.y+=w3.y; v.z+=w3.z; v.w+=w3.w; }
        if (in4) { float4 w4 = *(const float4*)(in4 + off); v.x+=w4.x; v.y+=w4.y; v.z+=w4.z; v.w+=w4.w; }
        if (reluIn) {
            v.x = fmaxf(v.x, 0.f); v.y = fmaxf(v.y, 0.f);
            v.z = fmaxf(v.z, 0.f); v.w = fmaxf(v.w, 0.f);
        }
        *(float4*)&Xs[k*PADN + n4] = v;
    }
    __syncthreads();
    const int tx = tid & 15, ty = tid >> 4;
    u64 acc[4][4] = {};
#pragma unroll 8
    for (int k = 0; k < 64; k++) {
        const float* mrow = &Ms[k*PADN + ty*8];
        ulonglong2 av0 = *(const ulonglong2*)(mrow);
        ulonglong2 av1 = *(const ulonglong2*)(mrow + 4);
        float4 xv = *(const float4*)&Xs[k*PADN + tx*4];
        u64 gs0 = splat2(xv.x), gs1 = splat2(xv.y), gs2 = splat2(xv.z), gs3 = splat2(xv.w);
        ffma2(acc[0][0], av0.x, gs0); ffma2(acc[0][1], av0.x, gs1);
        ffma2(acc[0][2], av0.x, gs2); ffma2(acc[0][3], av0.x, gs3);
        ffma2(acc[1][0], av0.y, gs0); ffma2(acc[1][1], av0.y, gs1);
        ffma2(acc[1][2], av0.y, gs2); ffma2(acc[1][3], av0.y, gs3);
        ffma2(acc[2][0], av1.x, gs0); ffma2(acc[2][1], av1.x, gs1);
        ffma2(acc[2][2], av1.x, gs2); ffma2(acc[2][3], av1.x, gs3);
        ffma2(acc[3][0], av1.y, gs0); ffma2(acc[3][1], av1.y, gs1);
        ffma2(acc[3][2], av1.y, gs2); ffma2(acc[3][3], av1.y, gs3);
    }
    // Ms is dead after this point; reuse it as staging for the transposed output.
    if (xTo) __syncthreads();
    float* outb = out + (size_t)b*outBstride + (size_t)z*CC*NN + n0;
    float* outb2 = out2 ? out2 + (size_t)b*outBstride + (size_t)z*CC*NN + n0 : nullptr;
    float4 sc = {1.f,1.f,1.f,1.f};
    if (outb2) {
        sc.x = scInv[tx*4]; sc.y = scInv[tx*4+1];
        sc.z = scInv[tx*4+2]; sc.w = scInv[tx*4+3];
    }
    float4 ps1 = {0.f,0.f,0.f,0.f};
    float4 ps2 = {0.f,0.f,0.f,0.f};
#pragma unroll
    for (int i = 0; i < 4; i++) {
        int o = ty*8 + 2*i;
        float b0 = bias ? bias[o]   : 0.f;
        float b1 = bias ? bias[o+1] : 0.f;
        float2 v0 = unpack2(acc[i][0]), v1 = unpack2(acc[i][1]);
        float2 v2 = unpack2(acc[i][2]), v3 = unpack2(acc[i][3]);
        float4 lo = {v0.x + b0, v1.x + b0, v2.x + b0, v3.x + b0};
        float4 hi = {v0.y + b1, v1.y + b1, v2.y + b1, v3.y + b1};
        if (roundOut) {
            lo.x = rnd_tf32(lo.x); lo.y = rnd_tf32(lo.y);
            lo.z = rnd_tf32(lo.z); lo.w = rnd_tf32(lo.w);
            hi.x = rnd_tf32(hi.x); hi.y = rnd_tf32(hi.y);
            hi.z = rnd_tf32(hi.z); hi.w = rnd_tf32(hi.w);
        }
        if (attA) {
            float a1o = a1s[o], a1o1 = a1s[o+1];
            float a2o = a2s[o], a2o1 = a2s[o+1];
            ps1.x = fmaf(lo.x, a1o, fmaf(hi.x, a1o1, ps1.x));
            ps1.y = fmaf(lo.y, a1o, fmaf(hi.y, a1o1, ps1.y));
            ps1.z = fmaf(lo.z, a1o, fmaf(hi.z, a1o1, ps1.z));
            ps1.w = fmaf(lo.w, a1o, fmaf(hi.w, a1o1, ps1.w));
            ps2.x = fmaf(lo.x, a2o, fmaf(hi.x, a2o1, ps2.x));
            ps2.y = fmaf(lo.y, a2o, fmaf(hi.y, a2o1, ps2.y));
            ps2.z = fmaf(lo.z, a2o, fmaf(hi.z, a2o1, ps2.z));
            ps2.w = fmaf(lo.w, a2o, fmaf(hi.w, a2o1, ps2.w));
        }
        if (sqo) {
            ps1.x = fmaf(lo.x, lo.x, fmaf(hi.x, hi.x, ps1.x));
            ps1.y = fmaf(lo.y, lo.y, fmaf(hi.y, hi.y, ps1.y));
            ps1.z = fmaf(lo.z, lo.z, fmaf(hi.z, hi.z, ps1.z));
            ps1.w = fmaf(lo.w, lo.w, fmaf(hi.w, hi.w, ps1.w));
        }
        *(float4*)(outb + (size_t)o*NN + tx*4) = lo;
        *(float4*)(outb + (size_t)(o+1)*NN + tx*4) = hi;
        if (outb2) {
            float4 lo2 = {rnd_tf32(lo.x*sc.x), rnd_tf32(lo.y*sc.y),
                          rnd_tf32(lo.z*sc.z), rnd_tf32(lo.w*sc.w)};
            float4 hi2 = {rnd_tf32(hi.x*sc.x), rnd_tf32(hi.y*sc.y),
                          rnd_tf32(hi.z*sc.z), rnd_tf32(hi.w*sc.w)};
            *(float4*)(outb2 + (size_t)o*NN + tx*4) = lo2;
            *(float4*)(outb2 + (size_t)(o+1)*NN + tx*4) = hi2;
        }
        if (xTo) {
            const float* plo = &lo.x;
            const float* phi = &hi.x;
#pragma unroll
            for (int q = 0; q < 4; q++) {
                Ms[(tx*4 + q)*PADN + o]   = rnd_tf32(plo[q]);
                Ms[(tx*4 + q)*PADN + o+1] = rnd_tf32(phi[q]);
            }
        }
    }
    if (attA || sqo) {
        *(float4*)&redA[ty*64 + tx*4] = ps1;
        if (attA) *(float4*)&redB[ty*64 + tx*4] = ps2;
    }
    if (attA || sqo || xTo) __syncthreads();
    if (xTo) {
        // coalesced transposed write: row r (node n0+r), 32 cols per half-thread
        float* xTb = xTo + ((size_t)b*NN + n0) * CC;
        int r = tid >> 1, half = tid & 1;
        const float* srow = &Ms[r*PADN + half*32];
        float* drow = xTb + (size_t)r*CC + half*32;
#pragma unroll
        for (int q = 0; q < 32; q += 4)
            *(float4*)(drow + q) = *(const float4*)(srow + q);
    }
    if (attA || sqo) {
        if (tid < 64) {
            float sa = 0.f, sb = 0.f;
#pragma unroll
            for (int r = 0; r < 8; r++) {
                sa += redA[r*64 + tid];
                if (attA) sb += redB[r*64 + tid];
            }
            if (attA) {
                s1o[b*NN + n0 + tid] = sa;
                s2o[b*NN + n0 + tid] = sb;
            } else {
                sqo[b*NN + n0 + tid] = sa;
            }
        }
    }
}

// ---------------- attention row max + inv-sum ----------------
__global__ void k_attinv() {
    int b = blockIdx.y, t = threadIdx.x;
    const float* s2 = g_s2 + b*NN;
    __shared__ float sh[256];
    float mx = fmaxf(fmaxf(s2[t], s2[t+256]), fmaxf(s2[t+512], s2[t+768]));
    sh[t] = mx; __syncthreads();
    for (int o = 128; o > 0; o >>= 1) { if (t < o) sh[t] = fmaxf(sh[t], sh[t+o]); __syncthreads(); }
    float mxs2 = sh[0];

    int row = blockIdx.x * 8 + (t >> 5);
    int lane = t & 31;
    float s1v = g_s1[b*NN + row];
    float m = s1v + mxs2;
    m = (m > 0.f) ? m : 0.01f * m;
    float sum = 0.f;
    for (int j = lane; j < NN; j += 32) {
        float e = s1v + s2[j];
        e = (e > 0.f) ? e : 0.01f * e;
        sum += __expf(e - m);
    }
#pragma unroll
    for (int o = 16; o > 0; o >>= 1) sum += __shfl_down_sync(0xffffffffu, sum, o);
    if (lane == 0) {
        g_amx [b*NN + row] = m;
        g_ainv[b*NN + row] = 1.f / sum;
    }
}

// ---------------- layernorm stats + final fuse ----------------
__global__ void k_lnstats() {
    int b = blockIdx.x, path = blockIdx.y, t = threadIdx.x;
    size_t base = (size_t)b*(2*CC)*NN + (size_t)path*CC*NN;
    float s = 0.f, ss = 0.f;
    for (int i = t; i < CC*NN; i += 1024) {
        float v = g_sxa[base + i] + g_sxb[base + i];
        s += v; ss = fmaf(v, v, ss);
    }
    __shared__ float shs[1024], shq[1024];
    shs[t] = s; shq[t] = ss; __syncthreads();
    for (int o = 512; o > 0; o >>= 1) {
        if (t < o) { shs[t] += shs[t+o]; shq[t] += shq[t+o]; }
        __syncthreads();
    }
    if (t == 0) {
        float mean = shs[0] * (1.f/65536.f);
        float var  = shq[0] * (1.f/65536.f) - mean*mean;
        g_stats[(path*BB + b)*2 + 0] = mean;
        g_stats[(path*BB + b)*2 + 1] = rsqrtf(var + 1e-5f);
    }
}

__global__ void k_final(const float* __restrict__ ct, const float* __restrict__ ln_w,
                        const float* __restrict__ ln_b, float* __restrict__ out) {
    size_t idx = (size_t)blockIdx.x * 256 + threadIdx.x;
    int b  = (int)(idx / (CC*NN));
    int cn = (int)(idx % (CC*NN));
    float m1 = g_stats[b*2 + 0],            r1 = g_stats[b*2 + 1];
    float m2 = g_stats[(BB + b)*2 + 0],     r2 = g_stats[(BB + b)*2 + 1];
    float w = ln_w[cn], bb = ln_b[cn];
    size_t base = (size_t)b*(2*CC)*NN + cn;
    float z1v = g_sxa[base] + g_sxb[base];
    float z2v = g_sxa[base + (size_t)CC*NN] + g_sxb[base + (size_t)CC*NN];
    float xnew = (z1v - m1) * r1 * w + bb;
    float z2   = (z2v - m2) * r2 * w + bb;
    float ft = 0.5f * z2 * (1.f + erff(z2 * 0.70710678118654752f));
    float ctv = ct[idx];
    float ctn = xnew + ft * (ctv - xnew);
    float el  = (ctn > 0.f) ? ctn : expm1f(ctn);
    float xu  = g_xuai[idx];
    float ht  = xu + ft * (el - xu);
    out[idx] = ht;
    out[(size_t)BB*CC*NN + idx] = ctn;
}

// ---------------- host launch ----------------
struct DevPtrs {
    float *gl, *g1, *g2, *wr, *h0a, *hT, *xuai, *xuaiT;
    float *pa, *pb, *pc, *pd;
    float *l12, *l12s, *t12a, *t12b, *u12, *a12a, *a12b, *sxa, *sxb;
    float *s1, *s2, *sq;
    bool init;
};
static DevPtrs P = {};
static const int GRAM_SMEM = 2 * 128 * GSTRIDE_W * 4;

static void init_ptrs() {
    if (P.init) return;
    void* p;
#define GET(sym, field) cudaGetSymbolAddress(&p, sym); P.field = (float*)p;
    GET(g_gl, gl)   GET(g_g1, g1)   GET(g_g2, g2)
    GET(g_wr, wr)    GET(g_h0a, h0a) GET(g_hT, hT)
    GET(g_xuai, xuai) GET(g_xuaiT, xuaiT)
    GET(g_pa, pa)    GET(g_pb, pb)   GET(g_pc, pc)   GET(g_pd, pd)
    GET(g_l12, l12)  GET(g_l12s, l12s)
    GET(g_t12a, t12a) GET(g_t12b, t12b) GET(g_u12, u12)
    GET(g_a12a, a12a) GET(g_a12b, a12b) GET(g_sxa, sxa) GET(g_sxb, sxb)
    GET(g_s1, s1) GET(g_s2, s2) GET(g_sq, sq)
#undef GET
    cudaFuncSetAttribute(k_gram_mma, cudaFuncAttributeMaxDynamicSharedMemorySize, GRAM_SMEM);
    P.init = true;
}

extern "C" void kernel_launch(void* const* d_in, const int* in_sizes, int n_in,
                              void* d_out, int out_size) {
    const float* x      = (const float*)d_in[0];
    const float* ct     = (const float*)d_in[1];
    const float* graph  = (const float*)d_in[2];
    const float* emb_w  = (const float*)d_in[3];
    const float* emb_b  = (const float*)d_in[4];
    const float* emb2_w = (const float*)d_in[5];
    const float* emb2_b = (const float*)d_in[6];
    const float* att_W  = (const float*)d_in[7];
    const float* att_a  = (const float*)d_in[8];
    // d_in[9] = att_GL : unused (softmax output strictly positive => mask no-op)
    const float* uai_w  = (const float*)d_in[10];
    const float* uai_b  = (const float*)d_in[11];
    const float* lin1_w = (const float*)d_in[12];
    const float* lin2_w = (const float*)d_in[13];
    const float* lin2_b = (const float*)d_in[14];
    const float* ln_w   = (const float*)d_in[15];
    const float* ln_b   = (const float*)d_in[16];
    float* out = (float*)d_out;

    init_ptrs();

    const size_t GLSTRIDE = (size_t)NN * NN;
    const size_t SB = (size_t)CC * NN;
    const size_t DB = (size_t)2 * CC * NN;
    const dim3 gridC1(NN/64, BB, 1);
    const dim3 gridC2(NN/64, BB, 2);

    // laplacian d, then combined prep (lapT + wround + emb1)
    k_lap_d<<<dim3(NN, 2), 256>>>(graph);
    k_prep <<<dim3(1024, 4), 256>>>(graph, emb2_w, x, emb_w, emb_b);

    // embedding GEMM
    mma_gemm<<<dim3(8, BB/2, 4), 256>>>(P.h0a, DB, 128, P.wr, 0, 4,
                                        nullptr, nullptr, emb2_b,
                                        P.pa, P.pb, P.pc, P.pd, DB);

    // attention: hT chanmix with fused s1/s2 rank-1 scores
    chanmixD<<<gridC1, 128>>>(P.pa, P.pb, P.pc, P.pd, 0, SB, 0,
                              att_W, nullptr, att_W, nullptr, 1, 1, P.hT, SB,
                              nullptr, 0, att_a, P.s1, P.s2, nullptr, nullptr);
    k_attinv<<<dim3(NN/8, BB), 256>>>();
    mma_gemm_att<<<dim3(8, BB, 2), 256>>>(P.hT, SB, P.pa, P.pb, SB);

    // UAI chanmix with fused sumsq + coalesced transposed/rounded copy for gram
    chanmixD<<<gridC1, 128>>>(P.pa, P.pb, nullptr, nullptr, 1, SB, 0,
                              uai_w, uai_b, uai_w, uai_b, 0, 0, P.xuai, SB,
                              nullptr, 0, nullptr, nullptr, nullptr, P.sq, P.xuaiT);

    // learned adjacency: tensor-core gram + fused row partials
    k_gram_mma<<<dim3(8, 8, BB), 256, GRAM_SMEM>>>();

    // l1/l2 stacked propagation; rsinv derived from g_part in-block
    chanmixD<<<gridC2, 128>>>(P.xuai, nullptr, nullptr, nullptr, 0, SB, 0,
                              lin1_w, nullptr, lin2_w, lin2_b, 0, 1, P.l12, DB,
                              P.l12s, 1, nullptr, nullptr, nullptr, nullptr, nullptr);

    // merged: unit0 l12s@gl -> a12a/b ; unit1 l12@g1 -> t12a/b
    mma_gemm2<<<dim3(8, BB, 4), 256>>>(P.l12s, P.gl, GLSTRIDE,
                                       P.l12, P.g1, 0,
                                       P.a12a, P.a12b, P.t12a, P.t12b, DB);

    chanmixD<<<gridC2, 128>>>(P.t12a, P.t12b, nullptr, nullptr, 0, DB, SB,
                              lin1_w, nullptr, lin2_w, lin2_b, 0, 1, P.u12, DB,
                              nullptr, 0, nullptr, nullptr, nullptr, nullptr, nullptr);

    mma_gemm<<<dim3(8, BB, 2), 256>>>(P.u12, DB, 128, P.g2, 0, 2,
                                      P.a12a, P.a12b, nullptr,
                                      P.sxa, P.sxb, nullptr, nullptr, DB);

    // layernorm + gates + output
    k_lnstats<<<dim3(BB, 2), 1024>>>();
    k_final  <<<(BB*CC*NN)/256, 256>>>(ct, ln_w, ln_b, out);
}